// round 13
// baseline (speedup 1.0000x reference)
#include <cuda_runtime.h>
#include <cuda_fp16.h>
#include <cstdint>

#define N_NODES 50000
#define N_EDGES 800000
#define H 128

// ---------------- device scratch ----------------
__device__ __align__(16) float g_agg_msg[(size_t)N_NODES * H];
__device__ __align__(16) float g_agg_coord4[(size_t)N_NODES * 4];  // x,y,z,count
// Weights as 8x8 b16 ldmatrix tiles, fp16, k64 chunk images (8192 ushorts = 16KB each).
__device__ __align__(16) unsigned short g_W1b[5 * 8192];   // K=288 -> 4 full + tail
__device__ __align__(16) unsigned short g_W2b[2 * 8192];
__device__ __align__(16) unsigned short g_Wc1b[2 * 8192];
__device__ __align__(16) unsigned short g_Wn1b[4 * 8192];  // K=256
__device__ __align__(16) unsigned short g_Wn2b[2 * 8192];  // K=128
// h pre-converted to fp16 16B groups: [node][k32chunk(4)][group(4)] uint4
__device__ __align__(16) uint4 g_hbf[(size_t)N_NODES * 16];

// ---------------- helpers ----------------
__device__ __forceinline__ uint32_t smem_u32(const void* p) {
    uint32_t a;
    asm("{ .reg .u64 t; cvta.to.shared.u64 t, %1; cvt.u32.u64 %0, t; }" : "=r"(a) : "l"(p));
    return a;
}
__device__ __forceinline__ float h16rt(float v) {
    return __half2float(__float2half_rn(v));
}
__device__ __forceinline__ uint32_t pack2h(float a, float b) {
    __half2 hh = __floats2half2_rn(a, b);
    return *(uint32_t*)&hh;
}
__device__ __forceinline__ float silu_f(float v) {
    return v * (1.0f / (1.0f + __expf(-v)));
}
__device__ __forceinline__ void redv4(float* p, float a, float b, float c, float d) {
    asm volatile("red.global.add.v4.f32 [%0], {%1, %2, %3, %4};"
                 :: "l"(p), "f"(a), "f"(b), "f"(c), "f"(d) : "memory");
}
__device__ __forceinline__ void ldm4(uint32_t* r, uint32_t addr) {
    asm volatile("ldmatrix.sync.aligned.m8n8.x4.shared.b16 {%0,%1,%2,%3}, [%4];"
                 : "=r"(r[0]), "=r"(r[1]), "=r"(r[2]), "=r"(r[3]) : "r"(addr));
}
__device__ __forceinline__ void mma_f16(float* d, const uint32_t* a, uint32_t b0, uint32_t b1) {
    asm volatile("mma.sync.aligned.m16n8k16.row.col.f32.f16.f16.f32 "
                 "{%0,%1,%2,%3}, {%4,%5,%6,%7}, {%8,%9}, {%0,%1,%2,%3};"
                 : "+f"(d[0]), "+f"(d[1]), "+f"(d[2]), "+f"(d[3])
                 : "r"(a[0]), "r"(a[1]), "r"(a[2]), "r"(a[3]), "r"(b0), "r"(b1));
}
__device__ __forceinline__ void cp_async16(uint32_t dst, const void* src) {
    asm volatile("cp.async.cg.shared.global [%0], [%1], 16;" :: "r"(dst), "l"(src) : "memory");
}
#define CP_COMMIT  asm volatile("cp.async.commit_group;" ::: "memory")
#define CP_WAIT_0  asm volatile("cp.async.wait_group 0;" ::: "memory")

// A-plane XOR swizzle: 64B row stride, 16B groups permuted by g ^= (row>>1)&3.
__device__ __forceinline__ uint32_t aswz(int row, int byteInRow) {
    int g = byteInRow >> 4;
    int inner = byteInRow & 15;
    return (uint32_t)(row * 64 + (((g ^ ((row >> 1) & 3)) << 4) | inner));
}

// ---------------- smem layout (edge kernel) ----------------
#define AF_OFF   0         // 4 subslots x 8192
#define BB_OFF   32768     // B double buffer: 2 x 16384
#define BIAS_OFF 65536     // b1,b2,bc1,Wc2 : 4*512
#define REL_OFF  67584
#define EA_OFF   69120
#define DSQ_OFF  70656
#define SRC_OFF  71168
#define DST_OFF  71680
#define PW_OFF   72192
#define EDGE_SMEM 73216

// ---------------- smem layout (node kernel) ----------------
#define NSS_OFF  67584
#define NSQ_OFF  71680
#define NMU_OFF  75776
#define NINV_OFF 76288
#define NODE_SMEM 76800

// ---------------- zero / prep ----------------
__global__ void zero_kernel()
{
    int i = blockIdx.x * blockDim.x + threadIdx.x;
    if (i < N_NODES * H) g_agg_msg[i] = 0.0f;
    if (i < N_NODES * 4) g_agg_coord4[i] = 0.0f;
}

__global__ void hbf_kernel(const float* __restrict__ h)
{
    int idx = blockIdx.x * blockDim.x + threadIdx.x;
    if (idx >= N_NODES * 16) return;
    int node = idx >> 4;
    int gg = idx & 15;
    const float* src = h + (size_t)node * H + gg * 8;
    uint32_t w[4];
#pragma unroll
    for (int i = 0; i < 4; i++)
        w[i] = pack2h(src[i * 2], src[i * 2 + 1]);
    g_hbf[(size_t)node * 16 + gg] = make_uint4(w[0], w[1], w[2], w[3]);
}

__device__ __forceinline__ void prep_store(unsigned short* dst, int k, int n, float v)
{
    int chunk = k >> 6, ks = (k >> 4) & 3, khalf = (k >> 3) & 1, kin = k & 7;
    int nf = n >> 3, nin = n & 7;
    int tile = ks * 32 + nf * 2 + khalf;
    __half hh = __float2half_rn(v);
    dst[chunk * 8192 + tile * 64 + nin * 8 + kin] = *(unsigned short*)&hh;
}

// W1 only (has zero padding above Kact)
__global__ void prep_kernel(const float* __restrict__ W, int Kact, int Kpad)
{
    int idx = blockIdx.x * blockDim.x + threadIdx.x;
    if (idx >= 128 * Kpad) return;
    int k = idx >> 7, n = idx & 127;
    float v = (k < Kact) ? W[k * 128 + n] : 0.0f;
    prep_store(g_W1b, k, n, v);
}

// two unpadded weights in one launch
__global__ void prep2_kernel(const float* __restrict__ Wa, int whichA, int itemsA,
                             const float* __restrict__ Wb, int whichB, int itemsTotal)
{
    int idx = blockIdx.x * blockDim.x + threadIdx.x;
    if (idx >= itemsTotal) return;
    const float* W;
    int which;
    if (idx < itemsA) { W = Wa; which = whichA; }
    else              { W = Wb; which = whichB; idx -= itemsA; }
    int k = idx >> 7, n = idx & 127;
    unsigned short* dst = (which == 1) ? g_W2b : (which == 2) ? g_Wc1b :
                          (which == 3) ? g_Wn1b : g_Wn2b;
    prep_store(dst, k, n, W[k * 128 + n]);
}

// ---------------- shared mma pieces ----------------
__device__ __forceinline__ void init_d(float d[2][8][4], const float* sBias,
                                       int stage, int lane, int wc)
{
#pragma unroll
    for (int nf = 0; nf < 8; nf++) {
        int c0 = wc * 64 + nf * 8 + (lane & 3) * 2;
        float b0v = sBias[stage * 128 + c0];
        float b1v = sBias[stage * 128 + c0 + 1];
#pragma unroll
        for (int mf = 0; mf < 2; mf++) {
            d[mf][nf][0] = b0v; d[mf][nf][1] = b1v;
            d[mf][nf][2] = b0v; d[mf][nf][3] = b1v;
        }
    }
}

template<int NKS, bool TAIL>
__device__ __forceinline__ void do_mma(uint32_t sbase, uint32_t bBuf, uint32_t aOff,
                                       int lane, int wm, int wc, float d[2][8][4])
{
    uint32_t aRegion = sbase + AF_OFF + aOff;
    uint32_t bRow = (uint32_t)(((lane >> 3) << 7) + ((lane & 7) << 4));
#pragma unroll
    for (int ks = 0; ks < NKS; ks++) {
        int kbyte = (ks & 1) * 32 + ((lane & 16) ? 16 : 0);
        uint32_t subOff = (uint32_t)(ks >> 1) * 8192;
        uint32_t aHi[2][4], aLo[2][4];
#pragma unroll
        for (int mf = 0; mf < 2; mf++) {
            int row = wm * 32 + mf * 16 + (lane & 15);
            uint32_t ad = aRegion + subOff + aswz(row, kbyte);
            ldm4(aHi[mf], ad);
            if (TAIL) ldm4(aLo[mf], ad + 8192);
        }
        uint32_t tB = bBuf + (uint32_t)(ks * 32 + wc * 16) * 128 + bRow;
#pragma unroll
        for (int q = 0; q < 4; q++) {
            uint32_t bh[4];
            ldm4(bh, tB + q * 512);
#pragma unroll
            for (int j = 0; j < 2; j++) {
                int nf = q * 2 + j;
#pragma unroll
                for (int mf = 0; mf < 2; mf++) {
                    mma_f16(d[mf][nf], aHi[mf], bh[j * 2], bh[j * 2 + 1]);
                    if (TAIL) mma_f16(d[mf][nf], aLo[mf], bh[j * 2], bh[j * 2 + 1]);
                }
            }
        }
    }
}

__device__ __forceinline__ void silu_store_act(char* sb, float d[2][8][4],
                                               int lane, int wm, int wc)
{
#pragma unroll
    for (int mf = 0; mf < 2; mf++) {
        int r0 = wm * 32 + mf * 16 + (lane >> 2);
        int r1 = r0 + 8;
#pragma unroll
        for (int nf = 0; nf < 8; nf++) {
            int c0 = wc * 64 + nf * 8 + (lane & 3) * 2;
            float v0 = silu_f(d[mf][nf][0]);
            float v1 = silu_f(d[mf][nf][1]);
            float v2 = silu_f(d[mf][nf][2]);
            float v3 = silu_f(d[mf][nf][3]);
            int sub = c0 >> 5;
            int byte0 = (c0 & 31) * 2;
            char* subBase = sb + AF_OFF + sub * 8192;
            *(uint32_t*)(subBase + aswz(r0, byte0)) = pack2h(v0, v1);
            *(uint32_t*)(subBase + aswz(r1, byte0)) = pack2h(v2, v3);
        }
    }
}

// ---------------- edge kernel ----------------
__device__ __forceinline__ void issueB(uint32_t sbase, int cg, int tid)
{
    const unsigned short* gW;
    int cin;
    if (cg < 5)       { gW = g_W1b;  cin = cg; }
    else if (cg < 7)  { gW = g_W2b;  cin = cg - 5; }
    else              { gW = g_Wc1b; cin = cg - 7; }
    const uint4* bsrc = (const uint4*)(gW + (size_t)cin * 8192);
    uint32_t bdst = sbase + BB_OFF + (uint32_t)(cg & 1) * 16384;
    int niter = (cg == 4) ? 1 : 4;
#pragma unroll
    for (int i = 0; i < 4; i++) {
        if (i < niter)
            cp_async16(bdst + (uint32_t)(tid + i * 256) * 16, bsrc + tid + i * 256);
    }
    CP_COMMIT;
}

__device__ __forceinline__ void issueA(uint32_t sbase, int cn, const int* sSrc,
                                       const int* sDst, int row, int halfq)
{
    int node = ((cn < 2) ? sSrc : sDst)[row];
    const uint4* hbase = g_hbf + (size_t)node * 16 + (cn & 1) * 8;
    uint32_t dstBase = sbase + AF_OFF + (uint32_t)((cn & 1) * 2) * 8192;
#pragma unroll
    for (int sub = 0; sub < 2; sub++) {
#pragma unroll
        for (int j = 0; j < 2; j++) {
            int g = halfq * 2 + j;
            cp_async16(dstBase + (uint32_t)sub * 8192 + aswz(row, g * 16),
                       hbase + sub * 4 + g);
        }
    }
}

template<int STAGE>
__device__ __forceinline__ void epilogue(char* sb, float d[2][8][4],
                                         const int* sDst, const float* sRel,
                                         const float* bc2, float* sPw,
                                         int tid, int lane, int wm, int wc)
{
    __syncthreads();
    const float* sBias = (const float*)(sb + BIAS_OFF);
    float pw0[2] = {0.f, 0.f}, pw1[2] = {0.f, 0.f};
#pragma unroll
    for (int mf = 0; mf < 2; mf++) {
        int r0 = wm * 32 + mf * 16 + (lane >> 2);
        int r1 = r0 + 8;
#pragma unroll
        for (int nf = 0; nf < 8; nf++) {
            int c0 = wc * 64 + nf * 8 + (lane & 3) * 2;
            float v0 = silu_f(d[mf][nf][0]);
            float v1 = silu_f(d[mf][nf][1]);
            float v2 = silu_f(d[mf][nf][2]);
            float v3 = silu_f(d[mf][nf][3]);
            if (STAGE == 2) {
                float w0 = sBias[384 + c0], w1 = sBias[384 + c0 + 1];
                pw0[mf] += v0 * w0 + v1 * w1;
                pw1[mf] += v2 * w0 + v3 * w1;
            } else {
                if (STAGE == 1) {
                    // lane-pair redv4: even lane reduces row r0 cols [cb..cb+3],
                    // odd lane row r1. Neighbor (lane^1) owns cols c0^2.
                    float e0 = __shfl_xor_sync(0xffffffffu, v0, 1);
                    float e1 = __shfl_xor_sync(0xffffffffu, v1, 1);
                    float e2 = __shfl_xor_sync(0xffffffffu, v2, 1);
                    float e3 = __shfl_xor_sync(0xffffffffu, v3, 1);
                    int cb = wc * 64 + nf * 8 + ((lane & 2) << 1);
                    if ((lane & 1) == 0)
                        redv4(&g_agg_msg[(size_t)sDst[r0] * H + cb], v0, v1, e0, e1);
                    else
                        redv4(&g_agg_msg[(size_t)sDst[r1] * H + cb], e2, e3, v2, v3);
                }
                int sub = c0 >> 5;
                int byte0 = (c0 & 31) * 2;
                char* subBase = sb + AF_OFF + sub * 8192;
                *(uint32_t*)(subBase + aswz(r0, byte0)) = pack2h(v0, v1);
                *(uint32_t*)(subBase + aswz(r1, byte0)) = pack2h(v2, v3);
            }
        }
    }
    if (STAGE == 2) {
#pragma unroll
        for (int o = 1; o < 4; o <<= 1) {
            pw0[0] += __shfl_xor_sync(0xffffffffu, pw0[0], o);
            pw0[1] += __shfl_xor_sync(0xffffffffu, pw0[1], o);
            pw1[0] += __shfl_xor_sync(0xffffffffu, pw1[0], o);
            pw1[1] += __shfl_xor_sync(0xffffffffu, pw1[1], o);
        }
        if ((lane & 3) == 0) {
            int r = wm * 32 + (lane >> 2);
            sPw[wc * 128 + r]      = pw0[0];
            sPw[wc * 128 + r + 8]  = pw1[0];
            sPw[wc * 128 + r + 16] = pw0[1];
            sPw[wc * 128 + r + 24] = pw1[1];
        }
        __syncthreads();
        if (tid < 128) {
            float w = sPw[tid] + sPw[128 + tid] + bc2[0];
            int dd = sDst[tid];
            redv4(&g_agg_coord4[(size_t)dd * 4],
                  sRel[tid * 3 + 0] * w, sRel[tid * 3 + 1] * w, sRel[tid * 3 + 2] * w, 1.0f);
        }
    }
}

__global__ __launch_bounds__(256, 2) void edge_kernel(
    const float* __restrict__ x,
    const int*   __restrict__ ei, const float* __restrict__ ea,
    const float* __restrict__ b1, const float* __restrict__ b2,
    const float* __restrict__ bc1, const float* __restrict__ Wc2,
    const float* __restrict__ bc2)
{
    extern __shared__ char sb[];
    uint32_t sbase = smem_u32(sb);
    int tid = threadIdx.x, lane = tid & 31, wid = tid >> 5;
    int wm = wid & 3, wc = wid >> 2;
    int ebase = blockIdx.x * 128;

    float* sBias = (float*)(sb + BIAS_OFF);
    float* sRel  = (float*)(sb + REL_OFF);
    float* sEa   = (float*)(sb + EA_OFF);
    float* sDsq  = (float*)(sb + DSQ_OFF);
    int*   sSrc  = (int*)(sb + SRC_OFF);
    int*   sDst  = (int*)(sb + DST_OFF);
    float* sPw   = (float*)(sb + PW_OFF);

    if (tid < 128) {
        sBias[tid]       = b1[tid];
        sBias[128 + tid] = b2[tid];
        sBias[256 + tid] = bc1[tid];
        sBias[384 + tid] = Wc2[tid];
        int e = ebase + tid;
        int s = ei[e];
        int dd = ei[N_EDGES + e];
        sSrc[tid] = s; sDst[tid] = dd;
        float rx = x[s * 3 + 0] - x[dd * 3 + 0];
        float ry = x[s * 3 + 1] - x[dd * 3 + 1];
        float rz = x[s * 3 + 2] - x[dd * 3 + 2];
        sRel[tid * 3 + 0] = rx; sRel[tid * 3 + 1] = ry; sRel[tid * 3 + 2] = rz;
        sDsq[tid] = rx * rx + ry * ry + rz * rz;
        sEa[tid * 3 + 0] = ea[e * 3 + 0];
        sEa[tid * 3 + 1] = ea[e * 3 + 1];
        sEa[tid * 3 + 2] = ea[e * 3 + 2];
    }
    __syncthreads();

    float d[2][8][4];
    int row = tid >> 1, halfq = tid & 1;

    // STAGE 0 : 5 chunks (4x k64 + k32 tail)
    init_d(d, sBias, 0, lane, wc);
    issueA(sbase, 0, sSrc, sDst, row, halfq);
    issueB(sbase, 0, tid);
#pragma unroll 1
    for (int c = 0; c < 5; c++) {
        CP_WAIT_0;
        __syncthreads();
        bool pf = (c < 3);
        if (pf) issueA(sbase, c + 1, sSrc, sDst, row, halfq);
        issueB(sbase, c + 1, tid);
        uint32_t bBuf = sbase + BB_OFF + (uint32_t)(c & 1) * 16384;
        if (c == 4) do_mma<1, true>(sbase, bBuf, 0, lane, wm, wc, d);
        else        do_mma<4, false>(sbase, bBuf, (uint32_t)(c & 1) * 16384, lane, wm, wc, d);
        if (c == 3) {
            char* base = sb + AF_OFF + (halfq ? 8192 : 0);
            uint32_t* p0 = (uint32_t*)(base + aswz(row, 0));
            if (halfq == 0) {
                p0[0] = pack2h(sEa[row * 3 + 0], sEa[row * 3 + 1]);
                p0[1] = pack2h(sEa[row * 3 + 2], sDsq[row]);
            } else {
                float e0 = sEa[row * 3 + 0], e1 = sEa[row * 3 + 1];
                float e2 = sEa[row * 3 + 2], dq = sDsq[row];
                p0[0] = pack2h(e0 - h16rt(e0), e1 - h16rt(e1));
                p0[1] = pack2h(e2 - h16rt(e2), dq - h16rt(dq));
            }
            p0[2] = 0u; p0[3] = 0u;
            uint32_t* p1 = (uint32_t*)(base + aswz(row, 16));
            p1[0] = 0u; p1[1] = 0u; p1[2] = 0u; p1[3] = 0u;
        }
    }
    epilogue<0>(sb, d, sDst, sRel, bc2, sPw, tid, lane, wm, wc);

    // STAGE 1 : chunks 5,6
    init_d(d, sBias, 1, lane, wc);
#pragma unroll 1
    for (int c = 0; c < 2; c++) {
        int cg = 5 + c;
        CP_WAIT_0;
        __syncthreads();
        issueB(sbase, cg + 1, tid);
        do_mma<4, false>(sbase, sbase + BB_OFF + (uint32_t)(cg & 1) * 16384,
                         (uint32_t)c * 16384, lane, wm, wc, d);
    }
    epilogue<1>(sb, d, sDst, sRel, bc2, sPw, tid, lane, wm, wc);

    // STAGE 2 : chunks 7,8
    init_d(d, sBias, 2, lane, wc);
#pragma unroll 1
    for (int c = 0; c < 2; c++) {
        int cg = 7 + c;
        CP_WAIT_0;
        __syncthreads();
        if (cg < 8) issueB(sbase, cg + 1, tid);
        do_mma<4, false>(sbase, sbase + BB_OFF + (uint32_t)(cg & 1) * 16384,
                         (uint32_t)c * 16384, lane, wm, wc, d);
    }
    epilogue<2>(sb, d, sDst, sRel, bc2, sPw, tid, lane, wm, wc);
}

// ---------------- tensorized node kernel : 128 nodes / block ----------------
__device__ __forceinline__ void issueB_node(uint32_t sbase, int cg, int tid)
{
    const unsigned short* gW = (cg < 4) ? g_Wn1b : g_Wn2b;
    int cin = (cg < 4) ? cg : cg - 4;
    const uint4* bsrc = (const uint4*)(gW + (size_t)cin * 8192);
    uint32_t bdst = sbase + BB_OFF + (uint32_t)(cg & 1) * 16384;
#pragma unroll
    for (int i = 0; i < 4; i++)
        cp_async16(bdst + (uint32_t)(tid + i * 256) * 16, bsrc + tid + i * 256);
    CP_COMMIT;
}

__device__ __forceinline__ void issueA_node_h(uint32_t sbase, int cn, int nbase,
                                              int row, int halfq)
{
    int node = nbase + row;
    if (node >= N_NODES) node = N_NODES - 1;
    const uint4* hbase = g_hbf + (size_t)node * 16 + cn * 8;
    uint32_t dstBase = sbase + AF_OFF + (uint32_t)(cn * 2) * 8192;
#pragma unroll
    for (int sub = 0; sub < 2; sub++) {
#pragma unroll
        for (int j = 0; j < 2; j++) {
            int g = halfq * 2 + j;
            cp_async16(dstBase + (uint32_t)sub * 8192 + aswz(row, g * 16),
                       hbase + sub * 4 + g);
        }
    }
}

__device__ __forceinline__ void fill_agg(char* sb, int cn, int nbase, int row, int halfq)
{
    int node = nbase + row;
    if (node >= N_NODES) node = N_NODES - 1;
    char* dstBase = sb + AF_OFF + ((cn & 1) * 2) * 8192;
#pragma unroll
    for (int sub = 0; sub < 2; sub++) {
        const float* s = g_agg_msg + (size_t)node * H + (cn - 2) * 64 + sub * 32 + halfq * 16;
#pragma unroll
        for (int j = 0; j < 2; j++) {
            float4 a = *(const float4*)(s + j * 8);
            float4 b = *(const float4*)(s + j * 8 + 4);
            uint4 w = make_uint4(pack2h(a.x, a.y), pack2h(a.z, a.w),
                                 pack2h(b.x, b.y), pack2h(b.z, b.w));
            *(uint4*)(dstBase + sub * 8192 + aswz(row, (halfq * 2 + j) * 16)) = w;
        }
    }
}

__global__ __launch_bounds__(256, 2) void node_kernel_t(
    const float* __restrict__ h,   const float* __restrict__ x,
    const float* __restrict__ bn1, const float* __restrict__ bn2,
    const float* __restrict__ gamma, const float* __restrict__ beta,
    float* __restrict__ out_h, float* __restrict__ out_x)
{
    extern __shared__ char sb[];
    uint32_t sbase = smem_u32(sb);
    int tid = threadIdx.x, lane = tid & 31, wid = tid >> 5;
    int wm = wid & 3, wc = wid >> 2;
    int nbase = blockIdx.x * 128;

    float* sBias = (float*)(sb + BIAS_OFF);
    float* sS    = (float*)(sb + NSS_OFF);
    float* sQ    = (float*)(sb + NSQ_OFF);
    float* sMu   = (float*)(sb + NMU_OFF);
    float* sInv  = (float*)(sb + NINV_OFF);

    if (tid < 128) {
        sBias[tid]       = bn1[tid];
        sBias[128 + tid] = bn2[tid];
        sBias[256 + tid] = gamma[tid];
        sBias[384 + tid] = beta[tid];
    }

    int row = tid >> 1, halfq = tid & 1;
    float d[2][8][4];

    issueA_node_h(sbase, 0, nbase, row, halfq);
    issueB_node(sbase, 0, tid);
    __syncthreads();
    init_d(d, sBias, 0, lane, wc);

    // STAGE N0 : 4 chunks (K=256)
#pragma unroll 1
    for (int c = 0; c < 4; c++) {
        CP_WAIT_0;
        __syncthreads();
        if (c == 0) issueA_node_h(sbase, 1, nbase, row, halfq);
        issueB_node(sbase, c + 1, tid);
        do_mma<4, false>(sbase, sbase + BB_OFF + (uint32_t)(c & 1) * 16384,
                         (uint32_t)(c & 1) * 16384, lane, wm, wc, d);
        if (c == 1) fill_agg(sb, 2, nbase, row, halfq);
        if (c == 2) fill_agg(sb, 3, nbase, row, halfq);
    }
    __syncthreads();
    silu_store_act(sb, d, lane, wm, wc);
    init_d(d, sBias, 1, lane, wc);

    // STAGE N1 : 2 chunks (K=128)
#pragma unroll 1
    for (int c = 0; c < 2; c++) {
        CP_WAIT_0;
        __syncthreads();
        if (c == 0) issueB_node(sbase, 5, tid);
        do_mma<4, false>(sbase, sbase + BB_OFF + (uint32_t)((4 + c) & 1) * 16384,
                         (uint32_t)c * 16384, lane, wm, wc, d);
    }

    // epilogue: y = h + h_upd ; LayerNorm ; out_h ; x_out
    __syncthreads();
#pragma unroll
    for (int mf = 0; mf < 2; mf++) {
        int r0 = wm * 32 + mf * 16 + (lane >> 2);
        int r1 = r0 + 8;
        int n0 = nbase + r0, n1 = nbase + r1;
        size_t hb0 = (size_t)((n0 < N_NODES) ? n0 : N_NODES - 1) * H;
        size_t hb1 = (size_t)((n1 < N_NODES) ? n1 : N_NODES - 1) * H;
        float s0 = 0.f, q0 = 0.f, s1 = 0.f, q1 = 0.f;
#pragma unroll
        for (int nf = 0; nf < 8; nf++) {
            int c0 = wc * 64 + nf * 8 + (lane & 3) * 2;
            float2 h0 = *(const float2*)(h + hb0 + c0);
            float2 h1 = *(const float2*)(h + hb1 + c0);
            float y0 = d[mf][nf][0] + h0.x, y1 = d[mf][nf][1] + h0.y;
            float y2 = d[mf][nf][2] + h1.x, y3 = d[mf][nf][3] + h1.y;
            d[mf][nf][0] = y0; d[mf][nf][1] = y1;
            d[mf][nf][2] = y2; d[mf][nf][3] = y3;
            s0 += y0 + y1; q0 += y0 * y0 + y1 * y1;
            s1 += y2 + y3; q1 += y2 * y2 + y3 * y3;
        }
        int slot = wc * 4 + (lane & 3);
        sS[r0 * 8 + slot] = s0; sQ[r0 * 8 + slot] = q0;
        sS[r1 * 8 + slot] = s1; sQ[r1 * 8 + slot] = q1;
    }
    __syncthreads();
    if (tid < 128) {
        float s = 0.f, q = 0.f;
#pragma unroll
        for (int i = 0; i < 8; i++) { s += sS[tid * 8 + i]; q += sQ[tid * 8 + i]; }
        float mu = s * (1.0f / 128.0f);
        float var = q * (1.0f / 128.0f) - mu * mu;
        sMu[tid] = mu;
        sInv[tid] = rsqrtf(var + 1e-5f);
    }
    __syncthreads();
#pragma unroll
    for (int mf = 0; mf < 2; mf++) {
        int r0 = wm * 32 + mf * 16 + (lane >> 2);
        int r1 = r0 + 8;
        int n0 = nbase + r0, n1 = nbase + r1;
        float mu0 = sMu[r0], inv0 = sInv[r0];
        float mu1 = sMu[r1], inv1 = sInv[r1];
#pragma unroll
        for (int nf = 0; nf < 8; nf++) {
            int c0 = wc * 64 + nf * 8 + (lane & 3) * 2;
            float g0 = sBias[256 + c0], g1 = sBias[256 + c0 + 1];
            float be0 = sBias[384 + c0], be1 = sBias[384 + c0 + 1];
            if (n0 < N_NODES) {
                float2 o;
                o.x = (d[mf][nf][0] - mu0) * inv0 * g0 + be0;
                o.y = (d[mf][nf][1] - mu0) * inv0 * g1 + be1;
                *(float2*)(out_h + (size_t)n0 * H + c0) = o;
            }
            if (n1 < N_NODES) {
                float2 o;
                o.x = (d[mf][nf][2] - mu1) * inv1 * g0 + be0;
                o.y = (d[mf][nf][3] - mu1) * inv1 * g1 + be1;
                *(float2*)(out_h + (size_t)n1 * H + c0) = o;
            }
        }
    }
    for (int i = tid; i < 384; i += 256) {
        int r = i / 3, c = i % 3;
        int node = nbase + r;
        if (node < N_NODES) {
            float cnt = fmaxf(g_agg_coord4[(size_t)node * 4 + 3], 1.0f);
            out_x[(size_t)node * 3 + c] = x[(size_t)node * 3 + c]
                                        + g_agg_coord4[(size_t)node * 4 + c] / cnt;
        }
    }
}

// ---------------------------------------------------------------------------
extern "C" void kernel_launch(void* const* d_in, const int* in_sizes, int n_in,
                              void* d_out, int out_size)
{
    const float* h    = (const float*)d_in[0];
    const float* x    = (const float*)d_in[1];
    const int*   eidx = (const int*)  d_in[2];
    const float* ea   = (const float*)d_in[3];
    const float* W1   = (const float*)d_in[4];
    const float* b1   = (const float*)d_in[5];
    const float* W2   = (const float*)d_in[6];
    const float* b2   = (const float*)d_in[7];
    const float* Wc1  = (const float*)d_in[8];
    const float* bc1  = (const float*)d_in[9];
    const float* Wc2  = (const float*)d_in[10];
    const float* bc2  = (const float*)d_in[11];
    const float* Wn1  = (const float*)d_in[12];
    const float* bn1  = (const float*)d_in[13];
    const float* Wn2  = (const float*)d_in[14];
    const float* bn2  = (const float*)d_in[15];
    const float* gamma = (const float*)d_in[16];
    const float* beta  = (const float*)d_in[17];

    float* out_h = (float*)d_out;
    float* out_x = out_h + (size_t)N_NODES * H;

    cudaFuncSetAttribute(edge_kernel, cudaFuncAttributeMaxDynamicSharedMemorySize, EDGE_SMEM);
    cudaFuncSetAttribute(node_kernel_t, cudaFuncAttributeMaxDynamicSharedMemorySize, NODE_SMEM);

    // launch order arranged so edge_kernel is the 6th launch (ncu -s 5 -c 1 captures it)
    zero_kernel<<<(N_NODES * H + 255) / 256, 256>>>();                            // 1
    hbf_kernel<<<(N_NODES * 16 + 255) / 256, 256>>>(h);                           // 2
    prep_kernel<<<(128 * 288 + 255) / 256, 256>>>(W1, 260, 288);                  // 3
    prep2_kernel<<<(2 * 128 * 128 + 255) / 256, 256>>>(W2, 1, 128 * 128,
                                                       Wc1, 2, 2 * 128 * 128);    // 4
    prep2_kernel<<<(128 * 256 + 128 * 128 + 255) / 256, 256>>>(Wn1, 3, 128 * 256,
                                                       Wn2, 4, 128 * 256 + 128 * 128); // 5
    edge_kernel<<<N_EDGES / 128, 256, EDGE_SMEM>>>(x, eidx, ea, b1, b2, bc1, Wc2, bc2); // 6
    node_kernel_t<<<(N_NODES + 127) / 128, 256, NODE_SMEM>>>(h, x, bn1, bn2, gamma, beta,
                                                             out_h, out_x);       // 7
}

// round 14
// speedup vs baseline: 1.0801x; 1.0801x over previous
#include <cuda_runtime.h>
#include <cuda_fp16.h>
#include <cstdint>

#define N_NODES 50000
#define N_EDGES 800000
#define H 128

// ---------------- device scratch ----------------
__device__ __align__(16) float g_agg_msg[(size_t)N_NODES * H];
__device__ __align__(16) float g_agg_coord4[(size_t)N_NODES * 4];  // x,y,z,count
// Weights as 8x8 b16 ldmatrix tiles, fp16, k64 chunk images (8192 ushorts = 16KB each).
__device__ __align__(16) unsigned short g_W1b[4 * 8192];   // K rows 0..255 (tail handled in fp32)
__device__ __align__(16) unsigned short g_W2b[2 * 8192];
__device__ __align__(16) unsigned short g_Wc1b[2 * 8192];
__device__ __align__(16) unsigned short g_Wn1b[4 * 8192];  // K=256
__device__ __align__(16) unsigned short g_Wn2b[2 * 8192];  // K=128
// h pre-converted to fp16 16B groups: [node][k32chunk(4)][group(4)] uint4
__device__ __align__(16) uint4 g_hbf[(size_t)N_NODES * 16];

// ---------------- helpers ----------------
__device__ __forceinline__ uint32_t smem_u32(const void* p) {
    uint32_t a;
    asm("{ .reg .u64 t; cvta.to.shared.u64 t, %1; cvt.u32.u64 %0, t; }" : "=r"(a) : "l"(p));
    return a;
}
__device__ __forceinline__ uint32_t pack2h(float a, float b) {
    __half2 hh = __floats2half2_rn(a, b);
    return *(uint32_t*)&hh;
}
__device__ __forceinline__ float silu_f(float v) {
    return v * (1.0f / (1.0f + __expf(-v)));
}
__device__ __forceinline__ void redv2(float* p, float a, float b) {
    asm volatile("red.global.add.v2.f32 [%0], {%1, %2};" :: "l"(p), "f"(a), "f"(b) : "memory");
}
__device__ __forceinline__ void redv4(float* p, float a, float b, float c, float d) {
    asm volatile("red.global.add.v4.f32 [%0], {%1, %2, %3, %4};"
                 :: "l"(p), "f"(a), "f"(b), "f"(c), "f"(d) : "memory");
}
__device__ __forceinline__ void ldm4(uint32_t* r, uint32_t addr) {
    asm volatile("ldmatrix.sync.aligned.m8n8.x4.shared.b16 {%0,%1,%2,%3}, [%4];"
                 : "=r"(r[0]), "=r"(r[1]), "=r"(r[2]), "=r"(r[3]) : "r"(addr));
}
__device__ __forceinline__ void mma_f16(float* d, const uint32_t* a, uint32_t b0, uint32_t b1) {
    asm volatile("mma.sync.aligned.m16n8k16.row.col.f32.f16.f16.f32 "
                 "{%0,%1,%2,%3}, {%4,%5,%6,%7}, {%8,%9}, {%0,%1,%2,%3};"
                 : "+f"(d[0]), "+f"(d[1]), "+f"(d[2]), "+f"(d[3])
                 : "r"(a[0]), "r"(a[1]), "r"(a[2]), "r"(a[3]), "r"(b0), "r"(b1));
}
__device__ __forceinline__ void cp_async16(uint32_t dst, const void* src) {
    asm volatile("cp.async.cg.shared.global [%0], [%1], 16;" :: "r"(dst), "l"(src) : "memory");
}
#define CP_COMMIT  asm volatile("cp.async.commit_group;" ::: "memory")
#define CP_WAIT_0  asm volatile("cp.async.wait_group 0;" ::: "memory")

// A-plane XOR swizzle: 64B row stride, 16B groups permuted by g ^= (row>>1)&3.
__device__ __forceinline__ uint32_t aswz(int row, int byteInRow) {
    int g = byteInRow >> 4;
    int inner = byteInRow & 15;
    return (uint32_t)(row * 64 + (((g ^ ((row >> 1) & 3)) << 4) | inner));
}

// ---------------- smem layout (edge kernel) ----------------
#define AF_OFF   0         // 4 subslots x 8192
#define BB_OFF   32768     // B double buffer: 2 x 16384
#define BIAS_OFF 65536     // b1,b2,bc1,Wc2 : 4*512
#define REL_OFF  67584
#define EA_OFF   69120
#define DSQ_OFF  70656
#define SRC_OFF  71168
#define DST_OFF  71680
#define PW_OFF   72192
#define WT_OFF   73216     // W1 tail rows 256..259 : 4*128 f = 2048 B
#define EDGE_SMEM 75264

// ---------------- smem layout (node kernel) ----------------
#define NSS_OFF  67584
#define NSQ_OFF  71680
#define NMU_OFF  75776
#define NINV_OFF 76288
#define NODE_SMEM 76800

// ---------------- zero / prep ----------------
__global__ void zero_kernel()
{
    int i = blockIdx.x * blockDim.x + threadIdx.x;
    float4 z = make_float4(0.f, 0.f, 0.f, 0.f);
    if (i < N_NODES * 32) {
        ((float4*)g_agg_msg)[i] = z;
    } else {
        int j = i - N_NODES * 32;
        if (j < N_NODES) ((float4*)g_agg_coord4)[j] = z;
    }
}

__global__ void hbf_kernel(const float* __restrict__ h)
{
    int idx = blockIdx.x * blockDim.x + threadIdx.x;
    if (idx >= N_NODES * 16) return;
    int node = idx >> 4;
    int gg = idx & 15;
    const float* src = h + (size_t)node * H + gg * 8;
    uint32_t w[4];
#pragma unroll
    for (int i = 0; i < 4; i++)
        w[i] = pack2h(src[i * 2], src[i * 2 + 1]);
    g_hbf[(size_t)node * 16 + gg] = make_uint4(w[0], w[1], w[2], w[3]);
}

__device__ __forceinline__ void prep_store(unsigned short* dst, int k, int n, float v)
{
    int chunk = k >> 6, ks = (k >> 4) & 3, khalf = (k >> 3) & 1, kin = k & 7;
    int nf = n >> 3, nin = n & 7;
    int tile = ks * 32 + nf * 2 + khalf;
    __half hh = __float2half_rn(v);
    dst[chunk * 8192 + tile * 64 + nin * 8 + kin] = *(unsigned short*)&hh;
}

// all five weights in one launch (W1 only rows 0..255; tail stays fp32)
__global__ void prep_all(const float* __restrict__ W1, const float* __restrict__ W2,
                         const float* __restrict__ Wc1, const float* __restrict__ Wn1,
                         const float* __restrict__ Wn2)
{
    int idx = blockIdx.x * blockDim.x + threadIdx.x;
    if (idx >= 114688) return;
    const float* W;
    unsigned short* dst;
    if (idx < 32768)       { W = W1;  dst = g_W1b; }
    else if (idx < 49152)  { W = W2;  dst = g_W2b;  idx -= 32768; }
    else if (idx < 65536)  { W = Wc1; dst = g_Wc1b; idx -= 49152; }
    else if (idx < 98304)  { W = Wn1; dst = g_Wn1b; idx -= 65536; }
    else                   { W = Wn2; dst = g_Wn2b; idx -= 98304; }
    int k = idx >> 7, n = idx & 127;
    prep_store(dst, k, n, W[k * 128 + n]);
}

// ---------------- shared mma pieces ----------------
__device__ __forceinline__ void init_d(float d[2][8][4], const float* sBias,
                                       int stage, int lane, int wc)
{
#pragma unroll
    for (int nf = 0; nf < 8; nf++) {
        int c0 = wc * 64 + nf * 8 + (lane & 3) * 2;
        float b0v = sBias[stage * 128 + c0];
        float b1v = sBias[stage * 128 + c0 + 1];
#pragma unroll
        for (int mf = 0; mf < 2; mf++) {
            d[mf][nf][0] = b0v; d[mf][nf][1] = b1v;
            d[mf][nf][2] = b0v; d[mf][nf][3] = b1v;
        }
    }
}

__device__ __forceinline__ void do_mma(uint32_t sbase, uint32_t bBuf, uint32_t aOff,
                                       int lane, int wm, int wc, float d[2][8][4])
{
    uint32_t aRegion = sbase + AF_OFF + aOff;
    uint32_t bRow = (uint32_t)(((lane >> 3) << 7) + ((lane & 7) << 4));
#pragma unroll
    for (int ks = 0; ks < 4; ks++) {
        int kbyte = (ks & 1) * 32 + ((lane & 16) ? 16 : 0);
        uint32_t subOff = (uint32_t)(ks >> 1) * 8192;
        uint32_t aHi[2][4];
#pragma unroll
        for (int mf = 0; mf < 2; mf++) {
            int row = wm * 32 + mf * 16 + (lane & 15);
            ldm4(aHi[mf], aRegion + subOff + aswz(row, kbyte));
        }
        uint32_t tB = bBuf + (uint32_t)(ks * 32 + wc * 16) * 128 + bRow;
#pragma unroll
        for (int q = 0; q < 4; q++) {
            uint32_t bh[4];
            ldm4(bh, tB + q * 512);
#pragma unroll
            for (int j = 0; j < 2; j++) {
                int nf = q * 2 + j;
#pragma unroll
                for (int mf = 0; mf < 2; mf++)
                    mma_f16(d[mf][nf], aHi[mf], bh[j * 2], bh[j * 2 + 1]);
            }
        }
    }
}

__device__ __forceinline__ void silu_store_act(char* sb, float d[2][8][4],
                                               int lane, int wm, int wc)
{
#pragma unroll
    for (int mf = 0; mf < 2; mf++) {
        int r0 = wm * 32 + mf * 16 + (lane >> 2);
        int r1 = r0 + 8;
#pragma unroll
        for (int nf = 0; nf < 8; nf++) {
            int c0 = wc * 64 + nf * 8 + (lane & 3) * 2;
            float v0 = silu_f(d[mf][nf][0]);
            float v1 = silu_f(d[mf][nf][1]);
            float v2 = silu_f(d[mf][nf][2]);
            float v3 = silu_f(d[mf][nf][3]);
            int sub = c0 >> 5;
            int byte0 = (c0 & 31) * 2;
            char* subBase = sb + AF_OFF + sub * 8192;
            *(uint32_t*)(subBase + aswz(r0, byte0)) = pack2h(v0, v1);
            *(uint32_t*)(subBase + aswz(r1, byte0)) = pack2h(v2, v3);
        }
    }
}

// ---------------- edge kernel ----------------
// B schedule: cg 0..3 W1, cg 4,5 W2, cg 6,7 Wc1 (all full 16KB)
__device__ __forceinline__ void issueB(uint32_t sbase, int cg, int tid)
{
    const unsigned short* gW;
    int cin;
    if (cg < 4)       { gW = g_W1b;  cin = cg; }
    else if (cg < 6)  { gW = g_W2b;  cin = cg - 4; }
    else              { gW = g_Wc1b; cin = cg - 6; }
    const uint4* bsrc = (const uint4*)(gW + (size_t)cin * 8192);
    uint32_t bdst = sbase + BB_OFF + (uint32_t)(cg & 1) * 16384;
#pragma unroll
    for (int i = 0; i < 4; i++)
        cp_async16(bdst + (uint32_t)(tid + i * 256) * 16, bsrc + tid + i * 256);
    CP_COMMIT;
}

__device__ __forceinline__ void issueA(uint32_t sbase, int cn, const int* sSrc,
                                       const int* sDst, int row, int halfq)
{
    int node = ((cn < 2) ? sSrc : sDst)[row];
    const uint4* hbase = g_hbf + (size_t)node * 16 + (cn & 1) * 8;
    uint32_t dstBase = sbase + AF_OFF + (uint32_t)((cn & 1) * 2) * 8192;
#pragma unroll
    for (int sub = 0; sub < 2; sub++) {
#pragma unroll
        for (int j = 0; j < 2; j++) {
            int g = halfq * 2 + j;
            cp_async16(dstBase + (uint32_t)sub * 8192 + aswz(row, g * 16),
                       hbase + sub * 4 + g);
        }
    }
}

// STAGE 0: + exact fp32 tail (ea,dsq @ W1 rows 256..259), silu, store act
// STAGE 1: silu, store act, redv2 agg_msg
// STAGE 2: silu, dot Wc2, coord red
template<int STAGE>
__device__ __forceinline__ void epilogue(char* sb, float d[2][8][4],
                                         const int* sDst, const float* sRel,
                                         const float* bc2, float* sPw,
                                         int tid, int lane, int wm, int wc)
{
    __syncthreads();  // all warps done reading A / B
    const float* sBias = (const float*)(sb + BIAS_OFF);
    const float* sWt   = (const float*)(sb + WT_OFF);
    const float* sEa   = (const float*)(sb + EA_OFF);
    const float* sDsq  = (const float*)(sb + DSQ_OFF);
    float pw0[2] = {0.f, 0.f}, pw1[2] = {0.f, 0.f};
#pragma unroll
    for (int mf = 0; mf < 2; mf++) {
        int r0 = wm * 32 + mf * 16 + (lane >> 2);
        int r1 = r0 + 8;
        float a0r0, a1r0, a2r0, qr0, a0r1, a1r1, a2r1, qr1;
        if (STAGE == 0) {
            a0r0 = sEa[r0 * 3]; a1r0 = sEa[r0 * 3 + 1]; a2r0 = sEa[r0 * 3 + 2]; qr0 = sDsq[r0];
            a0r1 = sEa[r1 * 3]; a1r1 = sEa[r1 * 3 + 1]; a2r1 = sEa[r1 * 3 + 2]; qr1 = sDsq[r1];
        }
#pragma unroll
        for (int nf = 0; nf < 8; nf++) {
            int c0 = wc * 64 + nf * 8 + (lane & 3) * 2;
            float t0 = d[mf][nf][0], t1 = d[mf][nf][1];
            float t2 = d[mf][nf][2], t3 = d[mf][nf][3];
            if (STAGE == 0) {
                float2 w0 = *(const float2*)&sWt[c0];
                float2 w1 = *(const float2*)&sWt[128 + c0];
                float2 w2 = *(const float2*)&sWt[256 + c0];
                float2 w3 = *(const float2*)&sWt[384 + c0];
                t0 += a0r0 * w0.x + a1r0 * w1.x + a2r0 * w2.x + qr0 * w3.x;
                t1 += a0r0 * w0.y + a1r0 * w1.y + a2r0 * w2.y + qr0 * w3.y;
                t2 += a0r1 * w0.x + a1r1 * w1.x + a2r1 * w2.x + qr1 * w3.x;
                t3 += a0r1 * w0.y + a1r1 * w1.y + a2r1 * w2.y + qr1 * w3.y;
            }
            float v0 = silu_f(t0);
            float v1 = silu_f(t1);
            float v2 = silu_f(t2);
            float v3 = silu_f(t3);
            if (STAGE == 2) {
                float w0 = sBias[384 + c0], w1 = sBias[384 + c0 + 1];
                pw0[mf] += v0 * w0 + v1 * w1;
                pw1[mf] += v2 * w0 + v3 * w1;
            } else {
                if (STAGE == 1) {
                    redv2(&g_agg_msg[(size_t)sDst[r0] * H + c0], v0, v1);
                    redv2(&g_agg_msg[(size_t)sDst[r1] * H + c0], v2, v3);
                }
                int sub = c0 >> 5;
                int byte0 = (c0 & 31) * 2;
                char* subBase = sb + AF_OFF + sub * 8192;
                *(uint32_t*)(subBase + aswz(r0, byte0)) = pack2h(v0, v1);
                *(uint32_t*)(subBase + aswz(r1, byte0)) = pack2h(v2, v3);
            }
        }
    }
    if (STAGE == 2) {
#pragma unroll
        for (int o = 1; o < 4; o <<= 1) {
            pw0[0] += __shfl_xor_sync(0xffffffffu, pw0[0], o);
            pw0[1] += __shfl_xor_sync(0xffffffffu, pw0[1], o);
            pw1[0] += __shfl_xor_sync(0xffffffffu, pw1[0], o);
            pw1[1] += __shfl_xor_sync(0xffffffffu, pw1[1], o);
        }
        if ((lane & 3) == 0) {
            int r = wm * 32 + (lane >> 2);
            sPw[wc * 128 + r]      = pw0[0];
            sPw[wc * 128 + r + 8]  = pw1[0];
            sPw[wc * 128 + r + 16] = pw0[1];
            sPw[wc * 128 + r + 24] = pw1[1];
        }
        __syncthreads();
        if (tid < 128) {
            float w = sPw[tid] + sPw[128 + tid] + bc2[0];
            int dd = sDst[tid];
            redv4(&g_agg_coord4[(size_t)dd * 4],
                  sRel[tid * 3 + 0] * w, sRel[tid * 3 + 1] * w, sRel[tid * 3 + 2] * w, 1.0f);
        }
    }
}

__global__ __launch_bounds__(256, 2) void edge_kernel(
    const float* __restrict__ x,
    const int*   __restrict__ ei, const float* __restrict__ ea,
    const float* __restrict__ W1,
    const float* __restrict__ b1, const float* __restrict__ b2,
    const float* __restrict__ bc1, const float* __restrict__ Wc2,
    const float* __restrict__ bc2)
{
    extern __shared__ char sb[];
    uint32_t sbase = smem_u32(sb);
    int tid = threadIdx.x, lane = tid & 31, wid = tid >> 5;
    int wm = wid & 3, wc = wid >> 2;
    int ebase = blockIdx.x * 128;

    float* sBias = (float*)(sb + BIAS_OFF);
    float* sRel  = (float*)(sb + REL_OFF);
    float* sEa   = (float*)(sb + EA_OFF);
    float* sDsq  = (float*)(sb + DSQ_OFF);
    int*   sSrc  = (int*)(sb + SRC_OFF);
    int*   sDst  = (int*)(sb + DST_OFF);
    float* sPw   = (float*)(sb + PW_OFF);
    float* sWt   = (float*)(sb + WT_OFF);

    if (tid < 128) {
        sBias[tid]       = b1[tid];
        sBias[128 + tid] = b2[tid];
        sBias[256 + tid] = bc1[tid];
        sBias[384 + tid] = Wc2[tid];
        ((float4*)sWt)[tid] = ((const float4*)(W1 + 256 * 128))[tid];  // tail rows
        int e = ebase + tid;
        int s = ei[e];
        int dd = ei[N_EDGES + e];
        sSrc[tid] = s; sDst[tid] = dd;
        float rx = x[s * 3 + 0] - x[dd * 3 + 0];
        float ry = x[s * 3 + 1] - x[dd * 3 + 1];
        float rz = x[s * 3 + 2] - x[dd * 3 + 2];
        sRel[tid * 3 + 0] = rx; sRel[tid * 3 + 1] = ry; sRel[tid * 3 + 2] = rz;
        sDsq[tid] = rx * rx + ry * ry + rz * rz;
        sEa[tid * 3 + 0] = ea[e * 3 + 0];
        sEa[tid * 3 + 1] = ea[e * 3 + 1];
        sEa[tid * 3 + 2] = ea[e * 3 + 2];
    }
    __syncthreads();

    float d[2][8][4];
    int row = tid >> 1, halfq = tid & 1;

    // STAGE 0 : 4 uniform k64 chunks (tail folded into epilogue)
    init_d(d, sBias, 0, lane, wc);
    issueA(sbase, 0, sSrc, sDst, row, halfq);
    issueB(sbase, 0, tid);
#pragma unroll 1
    for (int c = 0; c < 4; c++) {
        CP_WAIT_0;
        __syncthreads();
        if (c < 3) issueA(sbase, c + 1, sSrc, sDst, row, halfq);
        issueB(sbase, c + 1, tid);   // c+1 in [1,4]
        do_mma(sbase, sbase + BB_OFF + (uint32_t)(c & 1) * 16384,
               (uint32_t)(c & 1) * 16384, lane, wm, wc, d);
    }
    epilogue<0>(sb, d, sDst, sRel, bc2, sPw, tid, lane, wm, wc);

    // STAGE 1 : chunks 4,5 (B(4) already in flight)
    init_d(d, sBias, 1, lane, wc);
#pragma unroll 1
    for (int c = 0; c < 2; c++) {
        int cg = 4 + c;
        CP_WAIT_0;
        __syncthreads();
        issueB(sbase, cg + 1, tid);  // 5,6
        do_mma(sbase, sbase + BB_OFF + (uint32_t)(cg & 1) * 16384,
               (uint32_t)c * 16384, lane, wm, wc, d);
    }
    epilogue<1>(sb, d, sDst, sRel, bc2, sPw, tid, lane, wm, wc);

    // STAGE 2 : chunks 6,7 (B(6) already in flight)
    init_d(d, sBias, 2, lane, wc);
#pragma unroll 1
    for (int c = 0; c < 2; c++) {
        int cg = 6 + c;
        CP_WAIT_0;
        __syncthreads();
        if (cg < 7) issueB(sbase, cg + 1, tid);
        do_mma(sbase, sbase + BB_OFF + (uint32_t)(cg & 1) * 16384,
               (uint32_t)c * 16384, lane, wm, wc, d);
    }
    epilogue<2>(sb, d, sDst, sRel, bc2, sPw, tid, lane, wm, wc);
}

// ---------------- tensorized node kernel : 128 nodes / block ----------------
__device__ __forceinline__ void issueB_node(uint32_t sbase, int cg, int tid)
{
    const unsigned short* gW = (cg < 4) ? g_Wn1b : g_Wn2b;
    int cin = (cg < 4) ? cg : cg - 4;
    const uint4* bsrc = (const uint4*)(gW + (size_t)cin * 8192);
    uint32_t bdst = sbase + BB_OFF + (uint32_t)(cg & 1) * 16384;
#pragma unroll
    for (int i = 0; i < 4; i++)
        cp_async16(bdst + (uint32_t)(tid + i * 256) * 16, bsrc + tid + i * 256);
    CP_COMMIT;
}

__device__ __forceinline__ void issueA_node_h(uint32_t sbase, int cn, int nbase,
                                              int row, int halfq)
{
    int node = nbase + row;
    if (node >= N_NODES) node = N_NODES - 1;
    const uint4* hbase = g_hbf + (size_t)node * 16 + cn * 8;
    uint32_t dstBase = sbase + AF_OFF + (uint32_t)(cn * 2) * 8192;
#pragma unroll
    for (int sub = 0; sub < 2; sub++) {
#pragma unroll
        for (int j = 0; j < 2; j++) {
            int g = halfq * 2 + j;
            cp_async16(dstBase + (uint32_t)sub * 8192 + aswz(row, g * 16),
                       hbase + sub * 4 + g);
        }
    }
}

__device__ __forceinline__ void fill_agg(char* sb, int cn, int nbase, int row, int halfq)
{
    int node = nbase + row;
    if (node >= N_NODES) node = N_NODES - 1;
    char* dstBase = sb + AF_OFF + ((cn & 1) * 2) * 8192;
#pragma unroll
    for (int sub = 0; sub < 2; sub++) {
        const float* s = g_agg_msg + (size_t)node * H + (cn - 2) * 64 + sub * 32 + halfq * 16;
#pragma unroll
        for (int j = 0; j < 2; j++) {
            float4 a = *(const float4*)(s + j * 8);
            float4 b = *(const float4*)(s + j * 8 + 4);
            uint4 w = make_uint4(pack2h(a.x, a.y), pack2h(a.z, a.w),
                                 pack2h(b.x, b.y), pack2h(b.z, b.w));
            *(uint4*)(dstBase + sub * 8192 + aswz(row, (halfq * 2 + j) * 16)) = w;
        }
    }
}

__global__ __launch_bounds__(256, 2) void node_kernel_t(
    const float* __restrict__ h,   const float* __restrict__ x,
    const float* __restrict__ bn1, const float* __restrict__ bn2,
    const float* __restrict__ gamma, const float* __restrict__ beta,
    float* __restrict__ out_h, float* __restrict__ out_x)
{
    extern __shared__ char sb[];
    uint32_t sbase = smem_u32(sb);
    int tid = threadIdx.x, lane = tid & 31, wid = tid >> 5;
    int wm = wid & 3, wc = wid >> 2;
    int nbase = blockIdx.x * 128;

    float* sBias = (float*)(sb + BIAS_OFF);
    float* sS    = (float*)(sb + NSS_OFF);
    float* sQ    = (float*)(sb + NSQ_OFF);
    float* sMu   = (float*)(sb + NMU_OFF);
    float* sInv  = (float*)(sb + NINV_OFF);

    if (tid < 128) {
        sBias[tid]       = bn1[tid];
        sBias[128 + tid] = bn2[tid];
        sBias[256 + tid] = gamma[tid];
        sBias[384 + tid] = beta[tid];
    }

    int row = tid >> 1, halfq = tid & 1;
    float d[2][8][4];

    issueA_node_h(sbase, 0, nbase, row, halfq);
    issueB_node(sbase, 0, tid);
    __syncthreads();
    init_d(d, sBias, 0, lane, wc);

    // STAGE N0 : 4 chunks (K=256)
#pragma unroll 1
    for (int c = 0; c < 4; c++) {
        CP_WAIT_0;
        __syncthreads();
        if (c == 0) issueA_node_h(sbase, 1, nbase, row, halfq);
        issueB_node(sbase, c + 1, tid);
        do_mma(sbase, sbase + BB_OFF + (uint32_t)(c & 1) * 16384,
               (uint32_t)(c & 1) * 16384, lane, wm, wc, d);
        if (c == 1) fill_agg(sb, 2, nbase, row, halfq);
        if (c == 2) fill_agg(sb, 3, nbase, row, halfq);
    }
    __syncthreads();
    silu_store_act(sb, d, lane, wm, wc);
    init_d(d, sBias, 1, lane, wc);

    // STAGE N1 : 2 chunks (K=128)
#pragma unroll 1
    for (int c = 0; c < 2; c++) {
        CP_WAIT_0;
        __syncthreads();
        if (c == 0) issueB_node(sbase, 5, tid);
        do_mma(sbase, sbase + BB_OFF + (uint32_t)((4 + c) & 1) * 16384,
               (uint32_t)c * 16384, lane, wm, wc, d);
    }

    // epilogue: y = h + h_upd ; LayerNorm ; out_h ; x_out
    __syncthreads();
#pragma unroll
    for (int mf = 0; mf < 2; mf++) {
        int r0 = wm * 32 + mf * 16 + (lane >> 2);
        int r1 = r0 + 8;
        int n0 = nbase + r0, n1 = nbase + r1;
        size_t hb0 = (size_t)((n0 < N_NODES) ? n0 : N_NODES - 1) * H;
        size_t hb1 = (size_t)((n1 < N_NODES) ? n1 : N_NODES - 1) * H;
        float s0 = 0.f, q0 = 0.f, s1 = 0.f, q1 = 0.f;
#pragma unroll
        for (int nf = 0; nf < 8; nf++) {
            int c0 = wc * 64 + nf * 8 + (lane & 3) * 2;
            float2 h0 = *(const float2*)(h + hb0 + c0);
            float2 h1 = *(const float2*)(h + hb1 + c0);
            float y0 = d[mf][nf][0] + h0.x, y1 = d[mf][nf][1] + h0.y;
            float y2 = d[mf][nf][2] + h1.x, y3 = d[mf][nf][3] + h1.y;
            d[mf][nf][0] = y0; d[mf][nf][1] = y1;
            d[mf][nf][2] = y2; d[mf][nf][3] = y3;
            s0 += y0 + y1; q0 += y0 * y0 + y1 * y1;
            s1 += y2 + y3; q1 += y2 * y2 + y3 * y3;
        }
        int slot = wc * 4 + (lane & 3);
        sS[r0 * 8 + slot] = s0; sQ[r0 * 8 + slot] = q0;
        sS[r1 * 8 + slot] = s1; sQ[r1 * 8 + slot] = q1;
    }
    __syncthreads();
    if (tid < 128) {
        float s = 0.f, q = 0.f;
#pragma unroll
        for (int i = 0; i < 8; i++) { s += sS[tid * 8 + i]; q += sQ[tid * 8 + i]; }
        float mu = s * (1.0f / 128.0f);
        float var = q * (1.0f / 128.0f) - mu * mu;
        sMu[tid] = mu;
        sInv[tid] = rsqrtf(var + 1e-5f);
    }
    __syncthreads();
#pragma unroll
    for (int mf = 0; mf < 2; mf++) {
        int r0 = wm * 32 + mf * 16 + (lane >> 2);
        int r1 = r0 + 8;
        int n0 = nbase + r0, n1 = nbase + r1;
        float mu0 = sMu[r0], inv0 = sInv[r0];
        float mu1 = sMu[r1], inv1 = sInv[r1];
#pragma unroll
        for (int nf = 0; nf < 8; nf++) {
            int c0 = wc * 64 + nf * 8 + (lane & 3) * 2;
            float g0 = sBias[256 + c0], g1 = sBias[256 + c0 + 1];
            float be0 = sBias[384 + c0], be1 = sBias[384 + c0 + 1];
            if (n0 < N_NODES) {
                float2 o;
                o.x = (d[mf][nf][0] - mu0) * inv0 * g0 + be0;
                o.y = (d[mf][nf][1] - mu0) * inv0 * g1 + be1;
                *(float2*)(out_h + (size_t)n0 * H + c0) = o;
            }
            if (n1 < N_NODES) {
                float2 o;
                o.x = (d[mf][nf][2] - mu1) * inv1 * g0 + be0;
                o.y = (d[mf][nf][3] - mu1) * inv1 * g1 + be1;
                *(float2*)(out_h + (size_t)n1 * H + c0) = o;
            }
        }
    }
    for (int i = tid; i < 384; i += 256) {
        int r = i / 3, c = i % 3;
        int node = nbase + r;
        if (node < N_NODES) {
            float cnt = fmaxf(g_agg_coord4[(size_t)node * 4 + 3], 1.0f);
            out_x[(size_t)node * 3 + c] = x[(size_t)node * 3 + c]
                                        + g_agg_coord4[(size_t)node * 4 + c] / cnt;
        }
    }
}

// ---------------------------------------------------------------------------
extern "C" void kernel_launch(void* const* d_in, const int* in_sizes, int n_in,
                              void* d_out, int out_size)
{
    const float* h    = (const float*)d_in[0];
    const float* x    = (const float*)d_in[1];
    const int*   eidx = (const int*)  d_in[2];
    const float* ea   = (const float*)d_in[3];
    const float* W1   = (const float*)d_in[4];
    const float* b1   = (const float*)d_in[5];
    const float* W2   = (const float*)d_in[6];
    const float* b2   = (const float*)d_in[7];
    const float* Wc1  = (const float*)d_in[8];
    const float* bc1  = (const float*)d_in[9];
    const float* Wc2  = (const float*)d_in[10];
    const float* bc2  = (const float*)d_in[11];
    const float* Wn1  = (const float*)d_in[12];
    const float* bn1  = (const float*)d_in[13];
    const float* Wn2  = (const float*)d_in[14];
    const float* bn2  = (const float*)d_in[15];
    const float* gamma = (const float*)d_in[16];
    const float* beta  = (const float*)d_in[17];

    float* out_h = (float*)d_out;
    float* out_x = out_h + (size_t)N_NODES * H;

    cudaFuncSetAttribute(edge_kernel, cudaFuncAttributeMaxDynamicSharedMemorySize, EDGE_SMEM);
    cudaFuncSetAttribute(node_kernel_t, cudaFuncAttributeMaxDynamicSharedMemorySize, NODE_SMEM);

    zero_kernel<<<(N_NODES * 33 + 255) / 256, 256>>>();
    hbf_kernel<<<(N_NODES * 16 + 255) / 256, 256>>>(h);
    prep_all<<<(114688 + 255) / 256, 256>>>(W1, W2, Wc1, Wn1, Wn2);
    edge_kernel<<<N_EDGES / 128, 256, EDGE_SMEM>>>(x, eidx, ea, W1, b1, b2, bc1, Wc2, bc2);
    node_kernel_t<<<(N_NODES + 127) / 128, 256, NODE_SMEM>>>(h, x, bn1, bn2, gamma, beta,
                                                             out_h, out_x);
}

// round 15
// speedup vs baseline: 1.2236x; 1.1328x over previous
#include <cuda_runtime.h>
#include <cuda_fp16.h>
#include <cstdint>

#define N_NODES 50000
#define N_EDGES 800000
#define H 128

// ---------------- device scratch ----------------
__device__ __align__(16) float g_agg_msg[(size_t)N_NODES * H];
__device__ __align__(16) float g_agg_coord4[(size_t)N_NODES * 4];  // x,y,z,count
// Weights as 8x8 b16 ldmatrix tiles, fp16, k64 chunk images (8192 ushorts = 16KB each).
__device__ __align__(16) unsigned short g_W1b[4 * 8192];   // K rows 0..255 (tail in fp32)
__device__ __align__(16) unsigned short g_W2b[2 * 8192];
__device__ __align__(16) unsigned short g_Wc1b[2 * 8192];
__device__ __align__(16) unsigned short g_Wn1b[4 * 8192];  // K=256
__device__ __align__(16) unsigned short g_Wn2b[2 * 8192];  // K=128
// h pre-converted to fp16 16B groups: [node][k32chunk(4)][group(4)] uint4
__device__ __align__(16) uint4 g_hbf[(size_t)N_NODES * 16];

// ---------------- helpers ----------------
__device__ __forceinline__ uint32_t smem_u32(const void* p) {
    uint32_t a;
    asm("{ .reg .u64 t; cvta.to.shared.u64 t, %1; cvt.u32.u64 %0, t; }" : "=r"(a) : "l"(p));
    return a;
}
__device__ __forceinline__ uint32_t pack2h(float a, float b) {
    __half2 hh = __floats2half2_rn(a, b);
    return *(uint32_t*)&hh;
}
__device__ __forceinline__ float silu_f(float v) {
    return v * (1.0f / (1.0f + __expf(-v)));
}
__device__ __forceinline__ void redv2(float* p, float a, float b) {
    asm volatile("red.global.add.v2.f32 [%0], {%1, %2};" :: "l"(p), "f"(a), "f"(b) : "memory");
}
__device__ __forceinline__ void redv4(float* p, float a, float b, float c, float d) {
    asm volatile("red.global.add.v4.f32 [%0], {%1, %2, %3, %4};"
                 :: "l"(p), "f"(a), "f"(b), "f"(c), "f"(d) : "memory");
}
__device__ __forceinline__ void ldm4(uint32_t* r, uint32_t addr) {
    asm volatile("ldmatrix.sync.aligned.m8n8.x4.shared.b16 {%0,%1,%2,%3}, [%4];"
                 : "=r"(r[0]), "=r"(r[1]), "=r"(r[2]), "=r"(r[3]) : "r"(addr));
}
__device__ __forceinline__ void mma_f16(float* d, const uint32_t* a, uint32_t b0, uint32_t b1) {
    asm volatile("mma.sync.aligned.m16n8k16.row.col.f32.f16.f16.f32 "
                 "{%0,%1,%2,%3}, {%4,%5,%6,%7}, {%8,%9}, {%0,%1,%2,%3};"
                 : "+f"(d[0]), "+f"(d[1]), "+f"(d[2]), "+f"(d[3])
                 : "r"(a[0]), "r"(a[1]), "r"(a[2]), "r"(a[3]), "r"(b0), "r"(b1));
}
__device__ __forceinline__ void cp_async16(uint32_t dst, const void* src) {
    asm volatile("cp.async.cg.shared.global [%0], [%1], 16;" :: "r"(dst), "l"(src) : "memory");
}
#define CP_COMMIT  asm volatile("cp.async.commit_group;" ::: "memory")
#define CP_WAIT_0  asm volatile("cp.async.wait_group 0;" ::: "memory")

// A-plane XOR swizzle: 64B row stride, 16B groups permuted by g ^= (row>>1)&3.
__device__ __forceinline__ uint32_t aswz(int row, int byteInRow) {
    int g = byteInRow >> 4;
    int inner = byteInRow & 15;
    return (uint32_t)(row * 64 + (((g ^ ((row >> 1) & 3)) << 4) | inner));
}

// ---------------- smem layout (edge kernel) ----------------
#define AF_OFF   0         // 4 subslots x 8192
#define BB_OFF   32768     // B double buffer: 2 x 16384
#define BIAS_OFF 65536     // b1,b2,bc1,Wc2 : 4*512
#define REL_OFF  67584
#define EA_OFF   69120
#define DSQ_OFF  70656
#define SRC_OFF  71168
#define DST_OFF  71680
#define PW_OFF   72192     // 4*128 floats = 2048
#define WT_OFF   74240     // W1 tail rows 256..259 : 2048 B
#define EDGE_SMEM 76288

// ---------------- smem layout (node kernel) ----------------
#define NSS_OFF  67584     // 128*16 floats = 8192
#define NSQ_OFF  75776     // 8192
#define NMU_OFF  83968
#define NINV_OFF 84480
#define NODE_SMEM 84992

// ---------------- zero / prep ----------------
__global__ void zero_kernel()
{
    int i = blockIdx.x * blockDim.x + threadIdx.x;
    float4 z = make_float4(0.f, 0.f, 0.f, 0.f);
    if (i < N_NODES * 32) {
        ((float4*)g_agg_msg)[i] = z;
    } else {
        int j = i - N_NODES * 32;
        if (j < N_NODES) ((float4*)g_agg_coord4)[j] = z;
    }
}

__global__ void hbf_kernel(const float* __restrict__ h)
{
    int idx = blockIdx.x * blockDim.x + threadIdx.x;
    if (idx >= N_NODES * 16) return;
    int node = idx >> 4;
    int gg = idx & 15;
    const float* src = h + (size_t)node * H + gg * 8;
    uint32_t w[4];
#pragma unroll
    for (int i = 0; i < 4; i++)
        w[i] = pack2h(src[i * 2], src[i * 2 + 1]);
    g_hbf[(size_t)node * 16 + gg] = make_uint4(w[0], w[1], w[2], w[3]);
}

__device__ __forceinline__ void prep_store(unsigned short* dst, int k, int n, float v)
{
    int chunk = k >> 6, ks = (k >> 4) & 3, khalf = (k >> 3) & 1, kin = k & 7;
    int nf = n >> 3, nin = n & 7;
    int tile = ks * 32 + nf * 2 + khalf;
    __half hh = __float2half_rn(v);
    dst[chunk * 8192 + tile * 64 + nin * 8 + kin] = *(unsigned short*)&hh;
}

__global__ void prep_all(const float* __restrict__ W1, const float* __restrict__ W2,
                         const float* __restrict__ Wc1, const float* __restrict__ Wn1,
                         const float* __restrict__ Wn2)
{
    int idx = blockIdx.x * blockDim.x + threadIdx.x;
    if (idx >= 114688) return;
    const float* W;
    unsigned short* dst;
    if (idx < 32768)       { W = W1;  dst = g_W1b; }
    else if (idx < 49152)  { W = W2;  dst = g_W2b;  idx -= 32768; }
    else if (idx < 65536)  { W = Wc1; dst = g_Wc1b; idx -= 49152; }
    else if (idx < 98304)  { W = Wn1; dst = g_Wn1b; idx -= 65536; }
    else                   { W = Wn2; dst = g_Wn2b; idx -= 98304; }
    int k = idx >> 7, n = idx & 127;
    prep_store(dst, k, n, W[k * 128 + n]);
}

// ---------------- shared mma pieces (16 warps: wm=wid&3, wc=wid>>2, N=32/warp) ----------------
__device__ __forceinline__ void init_d(float d[2][4][4], const float* sBias,
                                       int stage, int lane, int wc)
{
#pragma unroll
    for (int nf = 0; nf < 4; nf++) {
        int c0 = wc * 32 + nf * 8 + (lane & 3) * 2;
        float b0v = sBias[stage * 128 + c0];
        float b1v = sBias[stage * 128 + c0 + 1];
#pragma unroll
        for (int mf = 0; mf < 2; mf++) {
            d[mf][nf][0] = b0v; d[mf][nf][1] = b1v;
            d[mf][nf][2] = b0v; d[mf][nf][3] = b1v;
        }
    }
}

__device__ __forceinline__ void do_mma(uint32_t sbase, uint32_t bBuf, uint32_t aOff,
                                       int lane, int wm, int wc, float d[2][4][4])
{
    uint32_t aRegion = sbase + AF_OFF + aOff;
    uint32_t bRow = (uint32_t)(((lane >> 3) << 7) + ((lane & 7) << 4));
#pragma unroll
    for (int ks = 0; ks < 4; ks++) {
        int kbyte = (ks & 1) * 32 + ((lane & 16) ? 16 : 0);
        uint32_t subOff = (uint32_t)(ks >> 1) * 8192;
        uint32_t aHi[2][4];
#pragma unroll
        for (int mf = 0; mf < 2; mf++) {
            int row = wm * 32 + mf * 16 + (lane & 15);
            ldm4(aHi[mf], aRegion + subOff + aswz(row, kbyte));
        }
        uint32_t tB = bBuf + (uint32_t)(ks * 32 + wc * 8) * 128 + bRow;
#pragma unroll
        for (int q = 0; q < 2; q++) {
            uint32_t bh[4];
            ldm4(bh, tB + q * 512);
#pragma unroll
            for (int j = 0; j < 2; j++) {
                int nf = q * 2 + j;
#pragma unroll
                for (int mf = 0; mf < 2; mf++)
                    mma_f16(d[mf][nf], aHi[mf], bh[j * 2], bh[j * 2 + 1]);
            }
        }
    }
}

__device__ __forceinline__ void silu_store_act(char* sb, float d[2][4][4],
                                               int lane, int wm, int wc)
{
#pragma unroll
    for (int mf = 0; mf < 2; mf++) {
        int r0 = wm * 32 + mf * 16 + (lane >> 2);
        int r1 = r0 + 8;
#pragma unroll
        for (int nf = 0; nf < 4; nf++) {
            int c0 = wc * 32 + nf * 8 + (lane & 3) * 2;
            float v0 = silu_f(d[mf][nf][0]);
            float v1 = silu_f(d[mf][nf][1]);
            float v2 = silu_f(d[mf][nf][2]);
            float v3 = silu_f(d[mf][nf][3]);
            char* subBase = sb + AF_OFF + wc * 8192;
            int byte0 = (c0 & 31) * 2;
            *(uint32_t*)(subBase + aswz(r0, byte0)) = pack2h(v0, v1);
            *(uint32_t*)(subBase + aswz(r1, byte0)) = pack2h(v2, v3);
        }
    }
}

// ---------------- edge kernel ----------------
// B schedule: cg 0..3 W1, cg 4,5 W2, cg 6,7 Wc1 (all full 16KB)
__device__ __forceinline__ void issueB(uint32_t sbase, int cg, int tid)
{
    const unsigned short* gW;
    int cin;
    if (cg < 4)       { gW = g_W1b;  cin = cg; }
    else if (cg < 6)  { gW = g_W2b;  cin = cg - 4; }
    else              { gW = g_Wc1b; cin = cg - 6; }
    const uint4* bsrc = (const uint4*)(gW + (size_t)cin * 8192);
    uint32_t bdst = sbase + BB_OFF + (uint32_t)(cg & 1) * 16384;
#pragma unroll
    for (int i = 0; i < 2; i++)
        cp_async16(bdst + (uint32_t)(tid + i * 512) * 16, bsrc + tid + i * 512);
    CP_COMMIT;
}

__device__ __forceinline__ void issueA(uint32_t sbase, int cn, const int* sSrc,
                                       const int* sDst, int row, int g)
{
    int node = ((cn < 2) ? sSrc : sDst)[row];
    const uint4* hbase = g_hbf + (size_t)node * 16 + (cn & 1) * 8;
    uint32_t dstBase = sbase + AF_OFF + (uint32_t)((cn & 1) * 2) * 8192;
    uint32_t off = aswz(row, g * 16);
    cp_async16(dstBase + off, hbase + g);
    cp_async16(dstBase + 8192 + off, hbase + 4 + g);
}

// STAGE 0: + exact fp32 tail, silu, store act
// STAGE 1: silu, store act, redv2 agg_msg
// STAGE 2: silu, dot Wc2, coord red
template<int STAGE>
__device__ __forceinline__ void epilogue(char* sb, float d[2][4][4],
                                         const int* sDst, const float* sRel,
                                         const float* bc2, float* sPw,
                                         int tid, int lane, int wm, int wc)
{
    __syncthreads();  // all warps done reading A / B
    const float* sBias = (const float*)(sb + BIAS_OFF);
    const float* sWt   = (const float*)(sb + WT_OFF);
    const float* sEa   = (const float*)(sb + EA_OFF);
    const float* sDsq  = (const float*)(sb + DSQ_OFF);
    float pw0[2] = {0.f, 0.f}, pw1[2] = {0.f, 0.f};
#pragma unroll
    for (int mf = 0; mf < 2; mf++) {
        int r0 = wm * 32 + mf * 16 + (lane >> 2);
        int r1 = r0 + 8;
        float a0r0, a1r0, a2r0, qr0, a0r1, a1r1, a2r1, qr1;
        if (STAGE == 0) {
            a0r0 = sEa[r0 * 3]; a1r0 = sEa[r0 * 3 + 1]; a2r0 = sEa[r0 * 3 + 2]; qr0 = sDsq[r0];
            a0r1 = sEa[r1 * 3]; a1r1 = sEa[r1 * 3 + 1]; a2r1 = sEa[r1 * 3 + 2]; qr1 = sDsq[r1];
        }
#pragma unroll
        for (int nf = 0; nf < 4; nf++) {
            int c0 = wc * 32 + nf * 8 + (lane & 3) * 2;
            float t0 = d[mf][nf][0], t1 = d[mf][nf][1];
            float t2 = d[mf][nf][2], t3 = d[mf][nf][3];
            if (STAGE == 0) {
                float2 w0 = *(const float2*)&sWt[c0];
                float2 w1 = *(const float2*)&sWt[128 + c0];
                float2 w2 = *(const float2*)&sWt[256 + c0];
                float2 w3 = *(const float2*)&sWt[384 + c0];
                t0 += a0r0 * w0.x + a1r0 * w1.x + a2r0 * w2.x + qr0 * w3.x;
                t1 += a0r0 * w0.y + a1r0 * w1.y + a2r0 * w2.y + qr0 * w3.y;
                t2 += a0r1 * w0.x + a1r1 * w1.x + a2r1 * w2.x + qr1 * w3.x;
                t3 += a0r1 * w0.y + a1r1 * w1.y + a2r1 * w2.y + qr1 * w3.y;
            }
            float v0 = silu_f(t0);
            float v1 = silu_f(t1);
            float v2 = silu_f(t2);
            float v3 = silu_f(t3);
            if (STAGE == 2) {
                float w0 = sBias[384 + c0], w1 = sBias[384 + c0 + 1];
                pw0[mf] += v0 * w0 + v1 * w1;
                pw1[mf] += v2 * w0 + v3 * w1;
            } else {
                if (STAGE == 1) {
                    redv2(&g_agg_msg[(size_t)sDst[r0] * H + c0], v0, v1);
                    redv2(&g_agg_msg[(size_t)sDst[r1] * H + c0], v2, v3);
                }
                char* subBase = sb + AF_OFF + wc * 8192;
                int byte0 = (c0 & 31) * 2;
                *(uint32_t*)(subBase + aswz(r0, byte0)) = pack2h(v0, v1);
                *(uint32_t*)(subBase + aswz(r1, byte0)) = pack2h(v2, v3);
            }
        }
    }
    if (STAGE == 2) {
#pragma unroll
        for (int o = 1; o < 4; o <<= 1) {
            pw0[0] += __shfl_xor_sync(0xffffffffu, pw0[0], o);
            pw0[1] += __shfl_xor_sync(0xffffffffu, pw0[1], o);
            pw1[0] += __shfl_xor_sync(0xffffffffu, pw1[0], o);
            pw1[1] += __shfl_xor_sync(0xffffffffu, pw1[1], o);
        }
        if ((lane & 3) == 0) {
            int r = wm * 32 + (lane >> 2);
            sPw[wc * 128 + r]      = pw0[0];
            sPw[wc * 128 + r + 8]  = pw1[0];
            sPw[wc * 128 + r + 16] = pw0[1];
            sPw[wc * 128 + r + 24] = pw1[1];
        }
        __syncthreads();
        if (tid < 128) {
            float w = sPw[tid] + sPw[128 + tid] + sPw[256 + tid] + sPw[384 + tid] + bc2[0];
            int dd = sDst[tid];
            redv4(&g_agg_coord4[(size_t)dd * 4],
                  sRel[tid * 3 + 0] * w, sRel[tid * 3 + 1] * w, sRel[tid * 3 + 2] * w, 1.0f);
        }
    }
}

__global__ __launch_bounds__(512, 2) void edge_kernel(
    const float* __restrict__ x,
    const int*   __restrict__ ei, const float* __restrict__ ea,
    const float* __restrict__ W1,
    const float* __restrict__ b1, const float* __restrict__ b2,
    const float* __restrict__ bc1, const float* __restrict__ Wc2,
    const float* __restrict__ bc2)
{
    extern __shared__ char sb[];
    uint32_t sbase = smem_u32(sb);
    int tid = threadIdx.x, lane = tid & 31, wid = tid >> 5;
    int wm = wid & 3, wc = wid >> 2;
    int ebase = blockIdx.x * 128;

    float* sBias = (float*)(sb + BIAS_OFF);
    float* sRel  = (float*)(sb + REL_OFF);
    float* sEa   = (float*)(sb + EA_OFF);
    float* sDsq  = (float*)(sb + DSQ_OFF);
    int*   sSrc  = (int*)(sb + SRC_OFF);
    int*   sDst  = (int*)(sb + DST_OFF);
    float* sPw   = (float*)(sb + PW_OFF);
    float* sWt   = (float*)(sb + WT_OFF);

    if (tid < 128) {
        sBias[tid]       = b1[tid];
        sBias[128 + tid] = b2[tid];
        sBias[256 + tid] = bc1[tid];
        sBias[384 + tid] = Wc2[tid];
        ((float4*)sWt)[tid] = ((const float4*)(W1 + 256 * 128))[tid];  // tail rows
        int e = ebase + tid;
        int s = ei[e];
        int dd = ei[N_EDGES + e];
        sSrc[tid] = s; sDst[tid] = dd;
        float rx = x[s * 3 + 0] - x[dd * 3 + 0];
        float ry = x[s * 3 + 1] - x[dd * 3 + 1];
        float rz = x[s * 3 + 2] - x[dd * 3 + 2];
        sRel[tid * 3 + 0] = rx; sRel[tid * 3 + 1] = ry; sRel[tid * 3 + 2] = rz;
        sDsq[tid] = rx * rx + ry * ry + rz * rz;
        sEa[tid * 3 + 0] = ea[e * 3 + 0];
        sEa[tid * 3 + 1] = ea[e * 3 + 1];
        sEa[tid * 3 + 2] = ea[e * 3 + 2];
    }
    __syncthreads();

    float d[2][4][4];
    int row = tid >> 2, g = tid & 3;

    // STAGE 0 : 4 uniform k64 chunks (tail folded into epilogue)
    init_d(d, sBias, 0, lane, wc);
    issueA(sbase, 0, sSrc, sDst, row, g);
    issueB(sbase, 0, tid);
#pragma unroll 1
    for (int c = 0; c < 4; c++) {
        CP_WAIT_0;
        __syncthreads();
        if (c < 3) issueA(sbase, c + 1, sSrc, sDst, row, g);
        issueB(sbase, c + 1, tid);   // c+1 in [1,4]
        do_mma(sbase, sbase + BB_OFF + (uint32_t)(c & 1) * 16384,
               (uint32_t)(c & 1) * 16384, lane, wm, wc, d);
    }
    epilogue<0>(sb, d, sDst, sRel, bc2, sPw, tid, lane, wm, wc);

    // STAGE 1 : chunks 4,5 (B(4) already in flight)
    init_d(d, sBias, 1, lane, wc);
#pragma unroll 1
    for (int c = 0; c < 2; c++) {
        int cg = 4 + c;
        CP_WAIT_0;
        __syncthreads();
        issueB(sbase, cg + 1, tid);  // 5,6
        do_mma(sbase, sbase + BB_OFF + (uint32_t)(cg & 1) * 16384,
               (uint32_t)c * 16384, lane, wm, wc, d);
    }
    epilogue<1>(sb, d, sDst, sRel, bc2, sPw, tid, lane, wm, wc);

    // STAGE 2 : chunks 6,7 (B(6) already in flight)
    init_d(d, sBias, 2, lane, wc);
#pragma unroll 1
    for (int c = 0; c < 2; c++) {
        int cg = 6 + c;
        CP_WAIT_0;
        __syncthreads();
        if (cg < 7) issueB(sbase, cg + 1, tid);
        do_mma(sbase, sbase + BB_OFF + (uint32_t)(cg & 1) * 16384,
               (uint32_t)c * 16384, lane, wm, wc, d);
    }
    epilogue<2>(sb, d, sDst, sRel, bc2, sPw, tid, lane, wm, wc);
}

// ---------------- tensorized node kernel : 128 nodes / block, 512 threads ----------------
__device__ __forceinline__ void issueB_node(uint32_t sbase, int cg, int tid)
{
    const unsigned short* gW = (cg < 4) ? g_Wn1b : g_Wn2b;
    int cin = (cg < 4) ? cg : cg - 4;
    const uint4* bsrc = (const uint4*)(gW + (size_t)cin * 8192);
    uint32_t bdst = sbase + BB_OFF + (uint32_t)(cg & 1) * 16384;
#pragma unroll
    for (int i = 0; i < 2; i++)
        cp_async16(bdst + (uint32_t)(tid + i * 512) * 16, bsrc + tid + i * 512);
    CP_COMMIT;
}

__device__ __forceinline__ void issueA_node_h(uint32_t sbase, int cn, int nbase,
                                              int row, int g)
{
    int node = nbase + row;
    if (node >= N_NODES) node = N_NODES - 1;
    const uint4* hbase = g_hbf + (size_t)node * 16 + cn * 8;
    uint32_t dstBase = sbase + AF_OFF + (uint32_t)(cn * 2) * 8192;
    uint32_t off = aswz(row, g * 16);
    cp_async16(dstBase + off, hbase + g);
    cp_async16(dstBase + 8192 + off, hbase + 4 + g);
}

__device__ __forceinline__ void fill_agg(char* sb, int cn, int nbase, int row, int g)
{
    int node = nbase + row;
    if (node >= N_NODES) node = N_NODES - 1;
    char* dstBase = sb + AF_OFF + ((cn & 1) * 2) * 8192;
    uint32_t off = aswz(row, g * 16);
#pragma unroll
    for (int sub = 0; sub < 2; sub++) {
        const float* s = g_agg_msg + (size_t)node * H + (cn - 2) * 64 + sub * 32 + g * 8;
        float4 a = *(const float4*)(s);
        float4 b = *(const float4*)(s + 4);
        uint4 w = make_uint4(pack2h(a.x, a.y), pack2h(a.z, a.w),
                             pack2h(b.x, b.y), pack2h(b.z, b.w));
        *(uint4*)(dstBase + sub * 8192 + off) = w;
    }
}

__global__ __launch_bounds__(512, 2) void node_kernel_t(
    const float* __restrict__ h,   const float* __restrict__ x,
    const float* __restrict__ bn1, const float* __restrict__ bn2,
    const float* __restrict__ gamma, const float* __restrict__ beta,
    float* __restrict__ out_h, float* __restrict__ out_x)
{
    extern __shared__ char sb[];
    uint32_t sbase = smem_u32(sb);
    int tid = threadIdx.x, lane = tid & 31, wid = tid >> 5;
    int wm = wid & 3, wc = wid >> 2;
    int nbase = blockIdx.x * 128;

    float* sBias = (float*)(sb + BIAS_OFF);
    float* sS    = (float*)(sb + NSS_OFF);
    float* sQ    = (float*)(sb + NSQ_OFF);
    float* sMu   = (float*)(sb + NMU_OFF);
    float* sInv  = (float*)(sb + NINV_OFF);

    if (tid < 128) {
        sBias[tid]       = bn1[tid];
        sBias[128 + tid] = bn2[tid];
        sBias[256 + tid] = gamma[tid];
        sBias[384 + tid] = beta[tid];
    }

    int row = tid >> 2, g = tid & 3;
    float d[2][4][4];

    issueA_node_h(sbase, 0, nbase, row, g);
    issueB_node(sbase, 0, tid);
    __syncthreads();
    init_d(d, sBias, 0, lane, wc);

    // STAGE N0 : 4 chunks (K=256)
#pragma unroll 1
    for (int c = 0; c < 4; c++) {
        CP_WAIT_0;
        __syncthreads();
        if (c == 0) issueA_node_h(sbase, 1, nbase, row, g);
        issueB_node(sbase, c + 1, tid);
        do_mma(sbase, sbase + BB_OFF + (uint32_t)(c & 1) * 16384,
               (uint32_t)(c & 1) * 16384, lane, wm, wc, d);
        if (c == 1) fill_agg(sb, 2, nbase, row, g);
        if (c == 2) fill_agg(sb, 3, nbase, row, g);
    }
    __syncthreads();
    silu_store_act(sb, d, lane, wm, wc);
    init_d(d, sBias, 1, lane, wc);

    // STAGE N1 : 2 chunks (K=128)
#pragma unroll 1
    for (int c = 0; c < 2; c++) {
        CP_WAIT_0;
        __syncthreads();
        if (c == 0) issueB_node(sbase, 5, tid);
        do_mma(sbase, sbase + BB_OFF + (uint32_t)((4 + c) & 1) * 16384,
               (uint32_t)c * 16384, lane, wm, wc, d);
    }

    // epilogue: y = h + h_upd ; LayerNorm ; out_h ; x_out
    __syncthreads();
#pragma unroll
    for (int mf = 0; mf < 2; mf++) {
        int r0 = wm * 32 + mf * 16 + (lane >> 2);
        int r1 = r0 + 8;
        int n0 = nbase + r0, n1 = nbase + r1;
        size_t hb0 = (size_t)((n0 < N_NODES) ? n0 : N_NODES - 1) * H;
        size_t hb1 = (size_t)((n1 < N_NODES) ? n1 : N_NODES - 1) * H;
        float s0 = 0.f, q0 = 0.f, s1 = 0.f, q1 = 0.f;
#pragma unroll
        for (int nf = 0; nf < 4; nf++) {
            int c0 = wc * 32 + nf * 8 + (lane & 3) * 2;
            float2 h0 = *(const float2*)(h + hb0 + c0);
            float2 h1 = *(const float2*)(h + hb1 + c0);
            float y0 = d[mf][nf][0] + h0.x, y1 = d[mf][nf][1] + h0.y;
            float y2 = d[mf][nf][2] + h1.x, y3 = d[mf][nf][3] + h1.y;
            d[mf][nf][0] = y0; d[mf][nf][1] = y1;
            d[mf][nf][2] = y2; d[mf][nf][3] = y3;
            s0 += y0 + y1; q0 += y0 * y0 + y1 * y1;
            s1 += y2 + y3; q1 += y2 * y2 + y3 * y3;
        }
        int slot = wc * 4 + (lane & 3);
        sS[r0 * 16 + slot] = s0; sQ[r0 * 16 + slot] = q0;
        sS[r1 * 16 + slot] = s1; sQ[r1 * 16 + slot] = q1;
    }
    __syncthreads();
    if (tid < 128) {
        float s = 0.f, q = 0.f;
#pragma unroll
        for (int i = 0; i < 16; i++) { s += sS[tid * 16 + i]; q += sQ[tid * 16 + i]; }
        float mu = s * (1.0f / 128.0f);
        float var = q * (1.0f / 128.0f) - mu * mu;
        sMu[tid] = mu;
        sInv[tid] = rsqrtf(var + 1e-5f);
    }
    __syncthreads();
#pragma unroll
    for (int mf = 0; mf < 2; mf++) {
        int r0 = wm * 32 + mf * 16 + (lane >> 2);
        int r1 = r0 + 8;
        int n0 = nbase + r0, n1 = nbase + r1;
        float mu0 = sMu[r0], inv0 = sInv[r0];
        float mu1 = sMu[r1], inv1 = sInv[r1];
#pragma unroll
        for (int nf = 0; nf < 4; nf++) {
            int c0 = wc * 32 + nf * 8 + (lane & 3) * 2;
            float g0 = sBias[256 + c0], g1 = sBias[256 + c0 + 1];
            float be0 = sBias[384 + c0], be1 = sBias[384 + c0 + 1];
            if (n0 < N_NODES) {
                float2 o;
                o.x = (d[mf][nf][0] - mu0) * inv0 * g0 + be0;
                o.y = (d[mf][nf][1] - mu0) * inv0 * g1 + be1;
                *(float2*)(out_h + (size_t)n0 * H + c0) = o;
            }
            if (n1 < N_NODES) {
                float2 o;
                o.x = (d[mf][nf][2] - mu1) * inv1 * g0 + be0;
                o.y = (d[mf][nf][3] - mu1) * inv1 * g1 + be1;
                *(float2*)(out_h + (size_t)n1 * H + c0) = o;
            }
        }
    }
    if (tid < 384) {
        int r = tid / 3, c = tid % 3;
        int node = nbase + r;
        if (node < N_NODES) {
            float cnt = fmaxf(g_agg_coord4[(size_t)node * 4 + 3], 1.0f);
            out_x[(size_t)node * 3 + c] = x[(size_t)node * 3 + c]
                                        + g_agg_coord4[(size_t)node * 4 + c] / cnt;
        }
    }
}

// ---------------------------------------------------------------------------
extern "C" void kernel_launch(void* const* d_in, const int* in_sizes, int n_in,
                              void* d_out, int out_size)
{
    const float* h    = (const float*)d_in[0];
    const float* x    = (const float*)d_in[1];
    const int*   eidx = (const int*)  d_in[2];
    const float* ea   = (const float*)d_in[3];
    const float* W1   = (const float*)d_in[4];
    const float* b1   = (const float*)d_in[5];
    const float* W2   = (const float*)d_in[6];
    const float* b2   = (const float*)d_in[7];
    const float* Wc1  = (const float*)d_in[8];
    const float* bc1  = (const float*)d_in[9];
    const float* Wc2  = (const float*)d_in[10];
    const float* bc2  = (const float*)d_in[11];
    const float* Wn1  = (const float*)d_in[12];
    const float* bn1  = (const float*)d_in[13];
    const float* Wn2  = (const float*)d_in[14];
    const float* bn2  = (const float*)d_in[15];
    const float* gamma = (const float*)d_in[16];
    const float* beta  = (const float*)d_in[17];

    float* out_h = (float*)d_out;
    float* out_x = out_h + (size_t)N_NODES * H;

    cudaFuncSetAttribute(edge_kernel, cudaFuncAttributeMaxDynamicSharedMemorySize, EDGE_SMEM);
    cudaFuncSetAttribute(node_kernel_t, cudaFuncAttributeMaxDynamicSharedMemorySize, NODE_SMEM);

    zero_kernel<<<(N_NODES * 33 + 255) / 256, 256>>>();
    hbf_kernel<<<(N_NODES * 16 + 255) / 256, 256>>>(h);
    prep_all<<<(114688 + 255) / 256, 256>>>(W1, W2, Wc1, Wn1, Wn2);
    edge_kernel<<<N_EDGES / 128, 512, EDGE_SMEM>>>(x, eidx, ea, W1, b1, b2, bc1, Wc2, bc2);
    node_kernel_t<<<(N_NODES + 127) / 128, 512, NODE_SMEM>>>(h, x, bn1, bn2, gamma, beta,
                                                             out_h, out_x);
}

// round 16
// speedup vs baseline: 1.4873x; 1.2155x over previous
#include <cuda_runtime.h>
#include <cuda_fp16.h>
#include <cstdint>

#define N_NODES 50000
#define N_EDGES 800000
#define H 128

// ---------------- device scratch ----------------
__device__ __align__(16) float g_agg_msg[(size_t)N_NODES * H];
__device__ __align__(16) float g_agg_coord4[(size_t)N_NODES * 4];  // x,y,z,count
// Weights as 8x8 b16 ldmatrix tiles, fp16, k64 chunk images (8192 ushorts = 16KB each).
__device__ __align__(16) unsigned short g_W1b[4 * 8192];   // K rows 0..255 (tail in fp32)
__device__ __align__(16) unsigned short g_W2b[2 * 8192];
__device__ __align__(16) unsigned short g_Wc1b[2 * 8192];
__device__ __align__(16) unsigned short g_Wn1b[4 * 8192];  // K=256
__device__ __align__(16) unsigned short g_Wn2b[2 * 8192];  // K=128
// h pre-converted to fp16 16B groups: [node][k32chunk(4)][group(4)] uint4
__device__ __align__(16) uint4 g_hbf[(size_t)N_NODES * 16];

// ---------------- helpers ----------------
__device__ __forceinline__ uint32_t smem_u32(const void* p) {
    uint32_t a;
    asm("{ .reg .u64 t; cvta.to.shared.u64 t, %1; cvt.u32.u64 %0, t; }" : "=r"(a) : "l"(p));
    return a;
}
__device__ __forceinline__ uint32_t pack2h(float a, float b) {
    __half2 hh = __floats2half2_rn(a, b);
    return *(uint32_t*)&hh;
}
// silu(v) = v*sigmoid(v) = hv + hv*tanh(hv), hv = v/2  (3 instr, 1 MUFU)
__device__ __forceinline__ float silu_f(float v) {
    float hv = 0.5f * v;
    float t;
    asm("tanh.approx.f32 %0, %1;" : "=f"(t) : "f"(hv));
    return fmaf(hv, t, hv);
}
__device__ __forceinline__ void redv2(float* p, float a, float b) {
    asm volatile("red.global.add.v2.f32 [%0], {%1, %2};" :: "l"(p), "f"(a), "f"(b) : "memory");
}
__device__ __forceinline__ void redv4(float* p, float a, float b, float c, float d) {
    asm volatile("red.global.add.v4.f32 [%0], {%1, %2, %3, %4};"
                 :: "l"(p), "f"(a), "f"(b), "f"(c), "f"(d) : "memory");
}
__device__ __forceinline__ void ldm4(uint32_t* r, uint32_t addr) {
    asm volatile("ldmatrix.sync.aligned.m8n8.x4.shared.b16 {%0,%1,%2,%3}, [%4];"
                 : "=r"(r[0]), "=r"(r[1]), "=r"(r[2]), "=r"(r[3]) : "r"(addr));
}
__device__ __forceinline__ void mma_f16(float* d, const uint32_t* a, uint32_t b0, uint32_t b1) {
    asm volatile("mma.sync.aligned.m16n8k16.row.col.f32.f16.f16.f32 "
                 "{%0,%1,%2,%3}, {%4,%5,%6,%7}, {%8,%9}, {%0,%1,%2,%3};"
                 : "+f"(d[0]), "+f"(d[1]), "+f"(d[2]), "+f"(d[3])
                 : "r"(a[0]), "r"(a[1]), "r"(a[2]), "r"(a[3]), "r"(b0), "r"(b1));
}
__device__ __forceinline__ void cp_async16(uint32_t dst, const void* src) {
    asm volatile("cp.async.cg.shared.global [%0], [%1], 16;" :: "r"(dst), "l"(src) : "memory");
}
#define CP_COMMIT  asm volatile("cp.async.commit_group;" ::: "memory")
#define CP_WAIT_0  asm volatile("cp.async.wait_group 0;" ::: "memory")

// A-plane XOR swizzle: 64B row stride, 16B groups permuted by g ^= (row>>1)&3.
__device__ __forceinline__ uint32_t aswz(int row, int byteInRow) {
    int g = byteInRow >> 4;
    int inner = byteInRow & 15;
    return (uint32_t)(row * 64 + (((g ^ ((row >> 1) & 3)) << 4) | inner));
}

// ---------------- smem layout (edge kernel) ----------------
#define AF_OFF   0         // 4 subslots x 8192
#define BB_OFF   32768     // B double buffer: 2 x 16384
#define BIAS_OFF 65536     // b1,b2,bc1,Wc2 : 4*512
#define REL_OFF  67584
#define EA_OFF   69120
#define DSQ_OFF  70656
#define SRC_OFF  71168
#define DST_OFF  71680
#define PW_OFF   72192     // 4*128 floats = 2048
#define WT_OFF   74240     // W1 tail rows 256..259 : 2048 B
#define WC1_OFF  76288     // resident Wc1: 2 chunks x 16KB
#define EDGE_SMEM 109056   // 106.5 KB -> 2 CTAs/SM (213 KB < 228 KB)

// ---------------- smem layout (node kernel) ----------------
#define NSS_OFF  67584     // 128*16 floats = 8192
#define NSQ_OFF  75776     // 8192
#define NMU_OFF  83968
#define NINV_OFF 84480
#define NODE_SMEM 84992

// ---------------- hbf + zero (one launch) ----------------
__global__ void hbfzero_kernel(const float* __restrict__ h)
{
    int idx = blockIdx.x * blockDim.x + threadIdx.x;
    if (idx >= N_NODES * 16) return;
    int node = idx >> 4;
    int gg = idx & 15;
    const float* src = h + (size_t)node * H + gg * 8;
    uint32_t w[4];
#pragma unroll
    for (int i = 0; i < 4; i++)
        w[i] = pack2h(src[i * 2], src[i * 2 + 1]);
    g_hbf[(size_t)node * 16 + gg] = make_uint4(w[0], w[1], w[2], w[3]);
    // zero scratch: agg_msg is 1.6M float4 (= 2 per thread), coord4 is 50k float4
    float4 z = make_float4(0.f, 0.f, 0.f, 0.f);
    ((float4*)g_agg_msg)[idx * 2]     = z;
    ((float4*)g_agg_msg)[idx * 2 + 1] = z;
    if (idx < N_NODES) ((float4*)g_agg_coord4)[idx] = z;
}

__device__ __forceinline__ void prep_store(unsigned short* dst, int k, int n, float v)
{
    int chunk = k >> 6, ks = (k >> 4) & 3, khalf = (k >> 3) & 1, kin = k & 7;
    int nf = n >> 3, nin = n & 7;
    int tile = ks * 32 + nf * 2 + khalf;
    __half hh = __float2half_rn(v);
    dst[chunk * 8192 + tile * 64 + nin * 8 + kin] = *(unsigned short*)&hh;
}

__global__ void prep_all(const float* __restrict__ W1, const float* __restrict__ W2,
                         const float* __restrict__ Wc1, const float* __restrict__ Wn1,
                         const float* __restrict__ Wn2)
{
    int idx = blockIdx.x * blockDim.x + threadIdx.x;
    if (idx >= 114688) return;
    const float* W;
    unsigned short* dst;
    if (idx < 32768)       { W = W1;  dst = g_W1b; }
    else if (idx < 49152)  { W = W2;  dst = g_W2b;  idx -= 32768; }
    else if (idx < 65536)  { W = Wc1; dst = g_Wc1b; idx -= 49152; }
    else if (idx < 98304)  { W = Wn1; dst = g_Wn1b; idx -= 65536; }
    else                   { W = Wn2; dst = g_Wn2b; idx -= 98304; }
    int k = idx >> 7, n = idx & 127;
    prep_store(dst, k, n, W[k * 128 + n]);
}

// ---------------- shared mma pieces (16 warps: wm=wid&3, wc=wid>>2, N=32/warp) ----------------
__device__ __forceinline__ void init_d(float d[2][4][4], const float* sBias,
                                       int stage, int lane, int wc)
{
#pragma unroll
    for (int nf = 0; nf < 4; nf++) {
        int c0 = wc * 32 + nf * 8 + (lane & 3) * 2;
        float b0v = sBias[stage * 128 + c0];
        float b1v = sBias[stage * 128 + c0 + 1];
#pragma unroll
        for (int mf = 0; mf < 2; mf++) {
            d[mf][nf][0] = b0v; d[mf][nf][1] = b1v;
            d[mf][nf][2] = b0v; d[mf][nf][3] = b1v;
        }
    }
}

__device__ __forceinline__ void do_mma(uint32_t sbase, uint32_t bBuf, uint32_t aOff,
                                       int lane, int wm, int wc, float d[2][4][4])
{
    uint32_t aRegion = sbase + AF_OFF + aOff;
    uint32_t bRow = (uint32_t)(((lane >> 3) << 7) + ((lane & 7) << 4));
#pragma unroll
    for (int ks = 0; ks < 4; ks++) {
        int kbyte = (ks & 1) * 32 + ((lane & 16) ? 16 : 0);
        uint32_t subOff = (uint32_t)(ks >> 1) * 8192;
        uint32_t aHi[2][4];
#pragma unroll
        for (int mf = 0; mf < 2; mf++) {
            int row = wm * 32 + mf * 16 + (lane & 15);
            ldm4(aHi[mf], aRegion + subOff + aswz(row, kbyte));
        }
        uint32_t tB = bBuf + (uint32_t)(ks * 32 + wc * 8) * 128 + bRow;
#pragma unroll
        for (int q = 0; q < 2; q++) {
            uint32_t bh[4];
            ldm4(bh, tB + q * 512);
#pragma unroll
            for (int j = 0; j < 2; j++) {
                int nf = q * 2 + j;
#pragma unroll
                for (int mf = 0; mf < 2; mf++)
                    mma_f16(d[mf][nf], aHi[mf], bh[j * 2], bh[j * 2 + 1]);
            }
        }
    }
}

// ---------------- edge kernel ----------------
// B double-buffer schedule: cg 0..3 W1, cg 4,5 W2. Wc1 is resident.
__device__ __forceinline__ void issueB(uint32_t sbase, int cg, int tid)
{
    const unsigned short* gW = (cg < 4) ? g_W1b : g_W2b;
    int cin = (cg < 4) ? cg : cg - 4;
    const uint4* bsrc = (const uint4*)(gW + (size_t)cin * 8192);
    uint32_t bdst = sbase + BB_OFF + (uint32_t)(cg & 1) * 16384;
#pragma unroll
    for (int i = 0; i < 2; i++)
        cp_async16(bdst + (uint32_t)(tid + i * 512) * 16, bsrc + tid + i * 512);
    CP_COMMIT;
}

__device__ __forceinline__ void issueA(uint32_t sbase, int cn, const int* sSrc,
                                       const int* sDst, int row, int g)
{
    int node = ((cn < 2) ? sSrc : sDst)[row];
    const uint4* hbase = g_hbf + (size_t)node * 16 + (cn & 1) * 8;
    uint32_t dstBase = sbase + AF_OFF + (uint32_t)((cn & 1) * 2) * 8192;
    uint32_t off = aswz(row, g * 16);
    cp_async16(dstBase + off, hbase + g);
    cp_async16(dstBase + 8192 + off, hbase + 4 + g);
}

// STAGE 0: + exact fp32 tail, silu, store act
// STAGE 1: silu, store act, redv2 agg_msg
// STAGE 2: silu, dot Wc2, coord red
template<int STAGE>
__device__ __forceinline__ void epilogue(char* sb, float d[2][4][4],
                                         const int* sDst, const float* sRel,
                                         const float* bc2, float* sPw,
                                         int tid, int lane, int wm, int wc)
{
    __syncthreads();  // all warps done reading A / B
    const float* sBias = (const float*)(sb + BIAS_OFF);
    const float* sWt   = (const float*)(sb + WT_OFF);
    const float* sEa   = (const float*)(sb + EA_OFF);
    const float* sDsq  = (const float*)(sb + DSQ_OFF);
    float pw0[2] = {0.f, 0.f}, pw1[2] = {0.f, 0.f};
#pragma unroll
    for (int mf = 0; mf < 2; mf++) {
        int r0 = wm * 32 + mf * 16 + (lane >> 2);
        int r1 = r0 + 8;
        float a0r0, a1r0, a2r0, qr0, a0r1, a1r1, a2r1, qr1;
        if (STAGE == 0) {
            a0r0 = sEa[r0 * 3]; a1r0 = sEa[r0 * 3 + 1]; a2r0 = sEa[r0 * 3 + 2]; qr0 = sDsq[r0];
            a0r1 = sEa[r1 * 3]; a1r1 = sEa[r1 * 3 + 1]; a2r1 = sEa[r1 * 3 + 2]; qr1 = sDsq[r1];
        }
#pragma unroll
        for (int nf = 0; nf < 4; nf++) {
            int c0 = wc * 32 + nf * 8 + (lane & 3) * 2;
            float t0 = d[mf][nf][0], t1 = d[mf][nf][1];
            float t2 = d[mf][nf][2], t3 = d[mf][nf][3];
            if (STAGE == 0) {
                float2 w0 = *(const float2*)&sWt[c0];
                float2 w1 = *(const float2*)&sWt[128 + c0];
                float2 w2 = *(const float2*)&sWt[256 + c0];
                float2 w3 = *(const float2*)&sWt[384 + c0];
                t0 += a0r0 * w0.x + a1r0 * w1.x + a2r0 * w2.x + qr0 * w3.x;
                t1 += a0r0 * w0.y + a1r0 * w1.y + a2r0 * w2.y + qr0 * w3.y;
                t2 += a0r1 * w0.x + a1r1 * w1.x + a2r1 * w2.x + qr1 * w3.x;
                t3 += a0r1 * w0.y + a1r1 * w1.y + a2r1 * w2.y + qr1 * w3.y;
            }
            float v0 = silu_f(t0);
            float v1 = silu_f(t1);
            float v2 = silu_f(t2);
            float v3 = silu_f(t3);
            if (STAGE == 2) {
                float w0 = sBias[384 + c0], w1 = sBias[384 + c0 + 1];
                pw0[mf] += v0 * w0 + v1 * w1;
                pw1[mf] += v2 * w0 + v3 * w1;
            } else {
                if (STAGE == 1) {
                    redv2(&g_agg_msg[(size_t)sDst[r0] * H + c0], v0, v1);
                    redv2(&g_agg_msg[(size_t)sDst[r1] * H + c0], v2, v3);
                }
                char* subBase = sb + AF_OFF + wc * 8192;
                int byte0 = (c0 & 31) * 2;
                *(uint32_t*)(subBase + aswz(r0, byte0)) = pack2h(v0, v1);
                *(uint32_t*)(subBase + aswz(r1, byte0)) = pack2h(v2, v3);
            }
        }
    }
    if (STAGE == 2) {
#pragma unroll
        for (int o = 1; o < 4; o <<= 1) {
            pw0[0] += __shfl_xor_sync(0xffffffffu, pw0[0], o);
            pw0[1] += __shfl_xor_sync(0xffffffffu, pw0[1], o);
            pw1[0] += __shfl_xor_sync(0xffffffffu, pw1[0], o);
            pw1[1] += __shfl_xor_sync(0xffffffffu, pw1[1], o);
        }
        if ((lane & 3) == 0) {
            int r = wm * 32 + (lane >> 2);
            sPw[wc * 128 + r]      = pw0[0];
            sPw[wc * 128 + r + 8]  = pw1[0];
            sPw[wc * 128 + r + 16] = pw0[1];
            sPw[wc * 128 + r + 24] = pw1[1];
        }
        __syncthreads();
        if (tid < 128) {
            float w = sPw[tid] + sPw[128 + tid] + sPw[256 + tid] + sPw[384 + tid] + bc2[0];
            int dd = sDst[tid];
            redv4(&g_agg_coord4[(size_t)dd * 4],
                  sRel[tid * 3 + 0] * w, sRel[tid * 3 + 1] * w, sRel[tid * 3 + 2] * w, 1.0f);
        }
    }
}

__global__ __launch_bounds__(512, 2) void edge_kernel(
    const float* __restrict__ x,
    const int*   __restrict__ ei, const float* __restrict__ ea,
    const float* __restrict__ W1,
    const float* __restrict__ b1, const float* __restrict__ b2,
    const float* __restrict__ bc1, const float* __restrict__ Wc2,
    const float* __restrict__ bc2)
{
    extern __shared__ char sb[];
    uint32_t sbase = smem_u32(sb);
    int tid = threadIdx.x, lane = tid & 31, wid = tid >> 5;
    int wm = wid & 3, wc = wid >> 2;
    int ebase = blockIdx.x * 128;

    float* sBias = (float*)(sb + BIAS_OFF);
    float* sRel  = (float*)(sb + REL_OFF);
    float* sEa   = (float*)(sb + EA_OFF);
    float* sDsq  = (float*)(sb + DSQ_OFF);
    int*   sSrc  = (int*)(sb + SRC_OFF);
    int*   sDst  = (int*)(sb + DST_OFF);
    float* sPw   = (float*)(sb + PW_OFF);
    float* sWt   = (float*)(sb + WT_OFF);

    // resident Wc1 (32KB) — own cp.async group, drained by first CP_WAIT_0
    {
        const uint4* src = (const uint4*)g_Wc1b;
        uint32_t dst = sbase + WC1_OFF;
#pragma unroll
        for (int i = 0; i < 4; i++)
            cp_async16(dst + (uint32_t)(tid + i * 512) * 16, src + tid + i * 512);
        CP_COMMIT;
    }

    if (tid < 128) {
        sBias[tid]       = b1[tid];
        sBias[128 + tid] = b2[tid];
        sBias[256 + tid] = bc1[tid];
        sBias[384 + tid] = Wc2[tid];
        ((float4*)sWt)[tid] = ((const float4*)(W1 + 256 * 128))[tid];  // tail rows
        int e = ebase + tid;
        int s = ei[e];
        int dd = ei[N_EDGES + e];
        sSrc[tid] = s; sDst[tid] = dd;
        float rx = x[s * 3 + 0] - x[dd * 3 + 0];
        float ry = x[s * 3 + 1] - x[dd * 3 + 1];
        float rz = x[s * 3 + 2] - x[dd * 3 + 2];
        sRel[tid * 3 + 0] = rx; sRel[tid * 3 + 1] = ry; sRel[tid * 3 + 2] = rz;
        sDsq[tid] = rx * rx + ry * ry + rz * rz;
        sEa[tid * 3 + 0] = ea[e * 3 + 0];
        sEa[tid * 3 + 1] = ea[e * 3 + 1];
        sEa[tid * 3 + 2] = ea[e * 3 + 2];
    }
    __syncthreads();

    float d[2][4][4];
    int row = tid >> 2, g = tid & 3;

    // STAGE 0 : 4 uniform k64 chunks (tail folded into epilogue)
    init_d(d, sBias, 0, lane, wc);
    issueA(sbase, 0, sSrc, sDst, row, g);
    issueB(sbase, 0, tid);
#pragma unroll 1
    for (int c = 0; c < 4; c++) {
        CP_WAIT_0;
        __syncthreads();
        if (c < 3) issueA(sbase, c + 1, sSrc, sDst, row, g);
        issueB(sbase, c + 1, tid);   // c+1 in [1,4]; cg=4 is W2 chunk 0
        do_mma(sbase, sbase + BB_OFF + (uint32_t)(c & 1) * 16384,
               (uint32_t)(c & 1) * 16384, lane, wm, wc, d);
    }
    epilogue<0>(sb, d, sDst, sRel, bc2, sPw, tid, lane, wm, wc);

    // STAGE 1 : chunks 4,5 (B(4) already in flight)
    init_d(d, sBias, 1, lane, wc);
#pragma unroll 1
    for (int c = 0; c < 2; c++) {
        int cg = 4 + c;
        CP_WAIT_0;
        __syncthreads();
        if (c == 0) issueB(sbase, 5, tid);
        do_mma(sbase, sbase + BB_OFF + (uint32_t)(cg & 1) * 16384,
               (uint32_t)c * 16384, lane, wm, wc, d);
    }
    epilogue<1>(sb, d, sDst, sRel, bc2, sPw, tid, lane, wm, wc);

    // STAGE 2 : resident Wc1, no waits — one barrier to publish epilogue-1 act
    init_d(d, sBias, 2, lane, wc);
    __syncthreads();
    do_mma(sbase, sbase + WC1_OFF,         0,     lane, wm, wc, d);
    do_mma(sbase, sbase + WC1_OFF + 16384, 16384, lane, wm, wc, d);
    epilogue<2>(sb, d, sDst, sRel, bc2, sPw, tid, lane, wm, wc);
}

// ---------------- tensorized node kernel : 128 nodes / block, 512 threads ----------------
__device__ __forceinline__ void issueB_node(uint32_t sbase, int cg, int tid)
{
    const unsigned short* gW = (cg < 4) ? g_Wn1b : g_Wn2b;
    int cin = (cg < 4) ? cg : cg - 4;
    const uint4* bsrc = (const uint4*)(gW + (size_t)cin * 8192);
    uint32_t bdst = sbase + BB_OFF + (uint32_t)(cg & 1) * 16384;
#pragma unroll
    for (int i = 0; i < 2; i++)
        cp_async16(bdst + (uint32_t)(tid + i * 512) * 16, bsrc + tid + i * 512);
    CP_COMMIT;
}

__device__ __forceinline__ void issueA_node_h(uint32_t sbase, int cn, int nbase,
                                              int row, int g)
{
    int node = nbase + row;
    if (node >= N_NODES) node = N_NODES - 1;
    const uint4* hbase = g_hbf + (size_t)node * 16 + cn * 8;
    uint32_t dstBase = sbase + AF_OFF + (uint32_t)(cn * 2) * 8192;
    uint32_t off = aswz(row, g * 16);
    cp_async16(dstBase + off, hbase + g);
    cp_async16(dstBase + 8192 + off, hbase + 4 + g);
}

__device__ __forceinline__ void fill_agg(char* sb, int cn, int nbase, int row, int g)
{
    int node = nbase + row;
    if (node >= N_NODES) node = N_NODES - 1;
    char* dstBase = sb + AF_OFF + ((cn & 1) * 2) * 8192;
    uint32_t off = aswz(row, g * 16);
#pragma unroll
    for (int sub = 0; sub < 2; sub++) {
        const float* s = g_agg_msg + (size_t)node * H + (cn - 2) * 64 + sub * 32 + g * 8;
        float4 a = *(const float4*)(s);
        float4 b = *(const float4*)(s + 4);
        uint4 w = make_uint4(pack2h(a.x, a.y), pack2h(a.z, a.w),
                             pack2h(b.x, b.y), pack2h(b.z, b.w));
        *(uint4*)(dstBase + sub * 8192 + off) = w;
    }
}

__device__ __forceinline__ void silu_store_act_n(char* sb, float d[2][4][4],
                                                 int lane, int wm, int wc)
{
#pragma unroll
    for (int mf = 0; mf < 2; mf++) {
        int r0 = wm * 32 + mf * 16 + (lane >> 2);
        int r1 = r0 + 8;
#pragma unroll
        for (int nf = 0; nf < 4; nf++) {
            int c0 = wc * 32 + nf * 8 + (lane & 3) * 2;
            float v0 = silu_f(d[mf][nf][0]);
            float v1 = silu_f(d[mf][nf][1]);
            float v2 = silu_f(d[mf][nf][2]);
            float v3 = silu_f(d[mf][nf][3]);
            char* subBase = sb + AF_OFF + wc * 8192;
            int byte0 = (c0 & 31) * 2;
            *(uint32_t*)(subBase + aswz(r0, byte0)) = pack2h(v0, v1);
            *(uint32_t*)(subBase + aswz(r1, byte0)) = pack2h(v2, v3);
        }
    }
}

__global__ __launch_bounds__(512, 2) void node_kernel_t(
    const float* __restrict__ h,   const float* __restrict__ x,
    const float* __restrict__ bn1, const float* __restrict__ bn2,
    const float* __restrict__ gamma, const float* __restrict__ beta,
    float* __restrict__ out_h, float* __restrict__ out_x)
{
    extern __shared__ char sb[];
    uint32_t sbase = smem_u32(sb);
    int tid = threadIdx.x, lane = tid & 31, wid = tid >> 5;
    int wm = wid & 3, wc = wid >> 2;
    int nbase = blockIdx.x * 128;

    float* sBias = (float*)(sb + BIAS_OFF);
    float* sS    = (float*)(sb + NSS_OFF);
    float* sQ    = (float*)(sb + NSQ_OFF);
    float* sMu   = (float*)(sb + NMU_OFF);
    float* sInv  = (float*)(sb + NINV_OFF);

    if (tid < 128) {
        sBias[tid]       = bn1[tid];
        sBias[128 + tid] = bn2[tid];
        sBias[256 + tid] = gamma[tid];
        sBias[384 + tid] = beta[tid];
    }

    int row = tid >> 2, g = tid & 3;
    float d[2][4][4];

    issueA_node_h(sbase, 0, nbase, row, g);
    issueB_node(sbase, 0, tid);
    __syncthreads();
    init_d(d, sBias, 0, lane, wc);

    // STAGE N0 : 4 chunks (K=256)
#pragma unroll 1
    for (int c = 0; c < 4; c++) {
        CP_WAIT_0;
        __syncthreads();
        if (c == 0) issueA_node_h(sbase, 1, nbase, row, g);
        issueB_node(sbase, c + 1, tid);
        do_mma(sbase, sbase + BB_OFF + (uint32_t)(c & 1) * 16384,
               (uint32_t)(c & 1) * 16384, lane, wm, wc, d);
        if (c == 1) fill_agg(sb, 2, nbase, row, g);
        if (c == 2) fill_agg(sb, 3, nbase, row, g);
    }
    __syncthreads();
    silu_store_act_n(sb, d, lane, wm, wc);
    init_d(d, sBias, 1, lane, wc);

    // STAGE N1 : 2 chunks (K=128)
#pragma unroll 1
    for (int c = 0; c < 2; c++) {
        CP_WAIT_0;
        __syncthreads();
        if (c == 0) issueB_node(sbase, 5, tid);
        do_mma(sbase, sbase + BB_OFF + (uint32_t)((4 + c) & 1) * 16384,
               (uint32_t)c * 16384, lane, wm, wc, d);
    }

    // epilogue: y = h + h_upd ; LayerNorm ; out_h ; x_out
    __syncthreads();
#pragma unroll
    for (int mf = 0; mf < 2; mf++) {
        int r0 = wm * 32 + mf * 16 + (lane >> 2);
        int r1 = r0 + 8;
        int n0 = nbase + r0, n1 = nbase + r1;
        size_t hb0 = (size_t)((n0 < N_NODES) ? n0 : N_NODES - 1) * H;
        size_t hb1 = (size_t)((n1 < N_NODES) ? n1 : N_NODES - 1) * H;
        float s0 = 0.f, q0 = 0.f, s1 = 0.f, q1 = 0.f;
#pragma unroll
        for (int nf = 0; nf < 4; nf++) {
            int c0 = wc * 32 + nf * 8 + (lane & 3) * 2;
            float2 h0 = *(const float2*)(h + hb0 + c0);
            float2 h1 = *(const float2*)(h + hb1 + c0);
            float y0 = d[mf][nf][0] + h0.x, y1 = d[mf][nf][1] + h0.y;
            float y2 = d[mf][nf][2] + h1.x, y3 = d[mf][nf][3] + h1.y;
            d[mf][nf][0] = y0; d[mf][nf][1] = y1;
            d[mf][nf][2] = y2; d[mf][nf][3] = y3;
            s0 += y0 + y1; q0 += y0 * y0 + y1 * y1;
            s1 += y2 + y3; q1 += y2 * y2 + y3 * y3;
        }
        int slot = wc * 4 + (lane & 3);
        sS[r0 * 16 + slot] = s0; sQ[r0 * 16 + slot] = q0;
        sS[r1 * 16 + slot] = s1; sQ[r1 * 16 + slot] = q1;
    }
    __syncthreads();
    if (tid < 128) {
        float s = 0.f, q = 0.f;
#pragma unroll
        for (int i = 0; i < 16; i++) { s += sS[tid * 16 + i]; q += sQ[tid * 16 + i]; }
        float mu = s * (1.0f / 128.0f);
        float var = q * (1.0f / 128.0f) - mu * mu;
        sMu[tid] = mu;
        sInv[tid] = rsqrtf(var + 1e-5f);
    }
    __syncthreads();
#pragma unroll
    for (int mf = 0; mf < 2; mf++) {
        int r0 = wm * 32 + mf * 16 + (lane >> 2);
        int r1 = r0 + 8;
        int n0 = nbase + r0, n1 = nbase + r1;
        float mu0 = sMu[r0], inv0 = sInv[r0];
        float mu1 = sMu[r1], inv1 = sInv[r1];
#pragma unroll
        for (int nf = 0; nf < 4; nf++) {
            int c0 = wc * 32 + nf * 8 + (lane & 3) * 2;
            float g0 = sBias[256 + c0], g1 = sBias[256 + c0 + 1];
            float be0 = sBias[384 + c0], be1 = sBias[384 + c0 + 1];
            if (n0 < N_NODES) {
                float2 o;
                o.x = (d[mf][nf][0] - mu0) * inv0 * g0 + be0;
                o.y = (d[mf][nf][1] - mu0) * inv0 * g1 + be1;
                *(float2*)(out_h + (size_t)n0 * H + c0) = o;
            }
            if (n1 < N_NODES) {
                float2 o;
                o.x = (d[mf][nf][2] - mu1) * inv1 * g0 + be0;
                o.y = (d[mf][nf][3] - mu1) * inv1 * g1 + be1;
                *(float2*)(out_h + (size_t)n1 * H + c0) = o;
            }
        }
    }
    if (tid < 384) {
        int r = tid / 3, c = tid % 3;
        int node = nbase + r;
        if (node < N_NODES) {
            float cnt = fmaxf(g_agg_coord4[(size_t)node * 4 + 3], 1.0f);
            out_x[(size_t)node * 3 + c] = x[(size_t)node * 3 + c]
                                        + g_agg_coord4[(size_t)node * 4 + c] / cnt;
        }
    }
}

// ---------------------------------------------------------------------------
extern "C" void kernel_launch(void* const* d_in, const int* in_sizes, int n_in,
                              void* d_out, int out_size)
{
    const float* h    = (const float*)d_in[0];
    const float* x    = (const float*)d_in[1];
    const int*   eidx = (const int*)  d_in[2];
    const float* ea   = (const float*)d_in[3];
    const float* W1   = (const float*)d_in[4];
    const float* b1   = (const float*)d_in[5];
    const float* W2   = (const float*)d_in[6];
    const float* b2   = (const float*)d_in[7];
    const float* Wc1  = (const float*)d_in[8];
    const float* bc1  = (const float*)d_in[9];
    const float* Wc2  = (const float*)d_in[10];
    const float* bc2  = (const float*)d_in[11];
    const float* Wn1  = (const float*)d_in[12];
    const float* bn1  = (const float*)d_in[13];
    const float* Wn2  = (const float*)d_in[14];
    const float* bn2  = (const float*)d_in[15];
    const float* gamma = (const float*)d_in[16];
    const float* beta  = (const float*)d_in[17];

    float* out_h = (float*)d_out;
    float* out_x = out_h + (size_t)N_NODES * H;

    cudaFuncSetAttribute(edge_kernel, cudaFuncAttributeMaxDynamicSharedMemorySize, EDGE_SMEM);
    cudaFuncSetAttribute(node_kernel_t, cudaFuncAttributeMaxDynamicSharedMemorySize, NODE_SMEM);

    hbfzero_kernel<<<(N_NODES * 16 + 255) / 256, 256>>>(h);
    prep_all<<<(114688 + 255) / 256, 256>>>(W1, W2, Wc1, Wn1, Wn2);
    edge_kernel<<<N_EDGES / 128, 512, EDGE_SMEM>>>(x, eidx, ea, W1, b1, b2, bc1, Wc2, bc2);
    node_kernel_t<<<(N_NODES + 127) / 128, 512, NODE_SMEM>>>(h, x, bn1, bn2, gamma, beta,
                                                             out_h, out_x);
}